// round 2
// baseline (speedup 1.0000x reference)
#include <cuda_runtime.h>
#include <cuda_bf16.h>
#include <math_constants.h>

// Problem shape (fixed by the reference): B=4, S=2048, D=1024
#define B_ 4
#define S_ 2048
#define D_ 1024
#define MTOT (B_ * S_)          // 8192 rows of x flattened

// ---------------------------------------------------------------------------
// Scratch (device globals: allocation-free per harness rules)
// ---------------------------------------------------------------------------
__device__ float g_Q[B_ * S_ * D_];          // 32 MB
__device__ float g_K[B_ * S_ * D_];          // 32 MB
__device__ float g_V[B_ * S_ * D_];          // 32 MB
__device__ float g_S[(size_t)B_ * S_ * S_];  // 64 MB (scores, then probs)

// ---------------------------------------------------------------------------
// 128x128x8 SGEMM bodies. 256 threads, each computes an 8x8 microtile.
//   NT: A[M,K] row-major, B[N,K] row-major  (C = A * B^T)
//   NN: A[M,K] row-major, B[K,N] row-major  (C = A * B)
// All dims are multiples of 128/8 for this problem -> no bounds checks.
// ---------------------------------------------------------------------------
__device__ __forceinline__ void gemm_nt_body(
    const float* __restrict__ A, const float* __restrict__ B,
    const float* __restrict__ bias, float* __restrict__ C,
    int N, int K, float scale)
{
    __shared__ float As[8][128];
    __shared__ float Bs[8][128];

    const int tid = threadIdx.x;
    const int bm  = blockIdx.y;
    const int bn  = blockIdx.x;
    const int tr  = (tid >> 4) << 3;   // 0..120 step 8 (C row offset in tile)
    const int tc  = (tid & 15) << 3;   // 0..120 step 8 (C col offset in tile)

    // global loads: each thread fetches one float4 along K for A and for B
    const int lrow = tid >> 1;         // 0..127
    const int lcol = (tid & 1) << 2;   // 0 or 4
    const float* Ap = A + (size_t)(bm * 128 + lrow) * K + lcol;
    const float* Bp = B + (size_t)(bn * 128 + lrow) * K + lcol;

    float acc[8][8];
#pragma unroll
    for (int i = 0; i < 8; i++)
#pragma unroll
        for (int j = 0; j < 8; j++) acc[i][j] = 0.0f;

    for (int k0 = 0; k0 < K; k0 += 8) {
        float4 av = *(const float4*)(Ap + k0);
        float4 bv = *(const float4*)(Bp + k0);
        __syncthreads();
        As[lcol + 0][lrow] = av.x; As[lcol + 1][lrow] = av.y;
        As[lcol + 2][lrow] = av.z; As[lcol + 3][lrow] = av.w;
        Bs[lcol + 0][lrow] = bv.x; Bs[lcol + 1][lrow] = bv.y;
        Bs[lcol + 2][lrow] = bv.z; Bs[lcol + 3][lrow] = bv.w;
        __syncthreads();
#pragma unroll
        for (int k = 0; k < 8; k++) {
            float a[8], b[8];
            *(float4*)&a[0] = *(const float4*)&As[k][tr];
            *(float4*)&a[4] = *(const float4*)&As[k][tr + 4];
            *(float4*)&b[0] = *(const float4*)&Bs[k][tc];
            *(float4*)&b[4] = *(const float4*)&Bs[k][tc + 4];
#pragma unroll
            for (int i = 0; i < 8; i++)
#pragma unroll
                for (int j = 0; j < 8; j++)
                    acc[i][j] = fmaf(a[i], b[j], acc[i][j]);
        }
    }

#pragma unroll
    for (int i = 0; i < 8; i++) {
        float* Crow = C + (size_t)(bm * 128 + tr + i) * N + bn * 128 + tc;
        float out[8];
#pragma unroll
        for (int j = 0; j < 8; j++) {
            float v = acc[i][j] * scale;
            if (bias) v += bias[bn * 128 + tc + j];
            out[j] = v;
        }
        *(float4*)&Crow[0] = *(const float4*)&out[0];
        *(float4*)&Crow[4] = *(const float4*)&out[4];
    }
}

__device__ __forceinline__ void gemm_nn_body(
    const float* __restrict__ A, const float* __restrict__ B,
    float* __restrict__ C, int N, int K)
{
    __shared__ float As[8][128];
    __shared__ float Bs[8][128];

    const int tid = threadIdx.x;
    const int bm  = blockIdx.y;
    const int bn  = blockIdx.x;
    const int tr  = (tid >> 4) << 3;
    const int tc  = (tid & 15) << 3;

    // A load (transpose into smem), same as NT
    const int lrow = tid >> 1;
    const int lcol = (tid & 1) << 2;
    const float* Ap = A + (size_t)(bm * 128 + lrow) * K + lcol;
    // B load: [8 x 128] slab, N-contiguous
    const int brow = tid >> 5;           // 0..7
    const int bcol = (tid & 31) << 2;    // 0..124
    const float* Bp = B + (size_t)brow * N + bn * 128 + bcol;

    float acc[8][8];
#pragma unroll
    for (int i = 0; i < 8; i++)
#pragma unroll
        for (int j = 0; j < 8; j++) acc[i][j] = 0.0f;

    for (int k0 = 0; k0 < K; k0 += 8) {
        float4 av = *(const float4*)(Ap + k0);
        float4 bv = *(const float4*)(Bp + (size_t)k0 * N);
        __syncthreads();
        As[lcol + 0][lrow] = av.x; As[lcol + 1][lrow] = av.y;
        As[lcol + 2][lrow] = av.z; As[lcol + 3][lrow] = av.w;
        *(float4*)&Bs[brow][bcol] = bv;
        __syncthreads();
#pragma unroll
        for (int k = 0; k < 8; k++) {
            float a[8], b[8];
            *(float4*)&a[0] = *(const float4*)&As[k][tr];
            *(float4*)&a[4] = *(const float4*)&As[k][tr + 4];
            *(float4*)&b[0] = *(const float4*)&Bs[k][tc];
            *(float4*)&b[4] = *(const float4*)&Bs[k][tc + 4];
#pragma unroll
            for (int i = 0; i < 8; i++)
#pragma unroll
                for (int j = 0; j < 8; j++)
                    acc[i][j] = fmaf(a[i], b[j], acc[i][j]);
        }
    }

#pragma unroll
    for (int i = 0; i < 8; i++) {
        float* Crow = C + (size_t)(bm * 128 + tr + i) * N + bn * 128 + tc;
        *(float4*)&Crow[0] = *(const float4*)&acc[i][0];
        *(float4*)&Crow[4] = *(const float4*)&acc[i][4];
    }
}

// ---------------------------------------------------------------------------
// Stage kernels
// ---------------------------------------------------------------------------

// grid (8, 64, 3): z selects Q/K/V. M=8192, N=1024, K=1024. out = x @ W^T + b
__global__ __launch_bounds__(256) void qkv_kernel(
    const float* __restrict__ x,
    const float* __restrict__ Wq, const float* __restrict__ bq,
    const float* __restrict__ Wk, const float* __restrict__ bk,
    const float* __restrict__ Wv, const float* __restrict__ bv)
{
    const float* W; const float* bias; float* out;
    if (blockIdx.z == 0)      { W = Wq; bias = bq; out = g_Q; }
    else if (blockIdx.z == 1) { W = Wk; bias = bk; out = g_K; }
    else                      { W = Wv; bias = bv; out = g_V; }
    gemm_nt_body(x, W, bias, out, D_, D_, 1.0f);
}

// grid (16, 16, 4): scores[b] = (Q[b] @ K[b]^T) / sqrt(D)
__global__ __launch_bounds__(256) void score_kernel()
{
    const int b = blockIdx.z;
    const float* Qb = g_Q + (size_t)b * S_ * D_;
    const float* Kb = g_K + (size_t)b * S_ * D_;
    float*       Sb = g_S + (size_t)b * S_ * S_;
    gemm_nt_body(Qb, Kb, nullptr, Sb, S_, D_, 0.03125f /* 1/sqrt(1024) */);
}

// grid (2048, 4), 256 threads: masked softmax over each score row (2048 keys)
// mask arrives as int32 (harness promotes numpy bool -> int32).
__global__ __launch_bounds__(256) void softmax_kernel(const int* __restrict__ mask)
{
    const int b = blockIdx.y;
    const int q = blockIdx.x;
    float* row = g_S + ((size_t)b * S_ + q) * S_;
    const int* m = mask + (size_t)b * S_;
    const int tid = threadIdx.x;

    __shared__ float red[256];

    float v[8];
    float mx = -CUDART_INF_F;
#pragma unroll
    for (int i = 0; i < 8; i++) {
        int k = tid + i * 256;
        float s = row[k];
        v[i] = (m[k] != 0) ? s : -CUDART_INF_F;
        mx = fmaxf(mx, v[i]);
    }
    red[tid] = mx;
    __syncthreads();
    for (int s = 128; s > 0; s >>= 1) {
        if (tid < s) red[tid] = fmaxf(red[tid], red[tid + s]);
        __syncthreads();
    }
    mx = red[0];
    __syncthreads();

    float sum = 0.0f;
#pragma unroll
    for (int i = 0; i < 8; i++) {
        float e = __expf(v[i] - mx);   // exp(-inf - mx) = 0 for masked keys
        v[i] = e;
        sum += e;
    }
    red[tid] = sum;
    __syncthreads();
    for (int s = 128; s > 0; s >>= 1) {
        if (tid < s) red[tid] += red[tid + s];
        __syncthreads();
    }
    const float inv = 1.0f / red[0];

#pragma unroll
    for (int i = 0; i < 8; i++) {
        int k = tid + i * 256;
        row[k] = v[i] * inv;
    }
}

// grid (8, 16, 4): out[b] = P[b] @ V[b]   (M=2048, N=1024, K=2048)
__global__ __launch_bounds__(256) void pv_kernel(float* __restrict__ out)
{
    const int b = blockIdx.z;
    const float* Pb = g_S + (size_t)b * S_ * S_;
    const float* Vb = g_V + (size_t)b * S_ * D_;
    float*       Ob = out + (size_t)b * S_ * D_;
    gemm_nn_body(Pb, Vb, Ob, D_, S_);
}

// ---------------------------------------------------------------------------
// Entry point (graph-capturable: kernel launches only, default stream)
// ---------------------------------------------------------------------------
extern "C" void kernel_launch(void* const* d_in, const int* in_sizes, int n_in,
                              void* d_out, int out_size)
{
    const float* x    = (const float*)d_in[0];
    const int*   mask = (const int*)d_in[1];   // numpy bool promoted to int32
    const float* Wq   = (const float*)d_in[2];
    const float* bq   = (const float*)d_in[3];
    const float* Wk   = (const float*)d_in[4];
    const float* bk   = (const float*)d_in[5];
    const float* Wv   = (const float*)d_in[6];
    const float* bv   = (const float*)d_in[7];
    float*       out  = (float*)d_out;

    dim3 blk(256);
    qkv_kernel   <<<dim3(D_ / 128, MTOT / 128, 3), blk>>>(x, Wq, bq, Wk, bk, Wv, bv);
    score_kernel <<<dim3(S_ / 128, S_ / 128, B_), blk>>>();
    softmax_kernel<<<dim3(S_, B_), blk>>>(mask);
    pv_kernel    <<<dim3(D_ / 128, S_ / 128, B_), blk>>>(out);
}

// round 4
// speedup vs baseline: 2.6597x; 2.6597x over previous
#include <cuda_runtime.h>
#include <cuda_bf16.h>
#include <math_constants.h>
#include <cstdint>

// Problem shape: B=4, S=2048, D=1024
#define B_ 4
#define S_ 2048
#define D_ 1024
#define MTOT (B_ * S_)   // 8192

typedef __nv_bfloat16 bf;

// Tiling: CTA 128x128, Kt=32 bf16 per stage, 3 stages, 4 operands (Ah,Al,Bh,Bl)
#define KT 32
#define OPER_B 8192                       // 128 rows * 64B
#define STAGE_B (4 * OPER_B)              // 32KB
#define NSTAGE 3
#define SMEM_TOTAL (NSTAGE * STAGE_B)     // 98304

// ---------------------------------------------------------------------------
// Scratch (device globals — allocation-free)
// ---------------------------------------------------------------------------
__device__ bf g_xh[MTOT * D_], g_xl[MTOT * D_];
__device__ bf g_Wh[3][D_ * D_], g_Wl[3][D_ * D_];
__device__ bf g_Qh[MTOT * D_], g_Ql[MTOT * D_];
__device__ bf g_Kh[MTOT * D_], g_Kl[MTOT * D_];
__device__ bf g_Vth[(size_t)B_ * D_ * S_], g_Vtl[(size_t)B_ * D_ * S_];
__device__ float g_S[(size_t)B_ * S_ * S_];
__device__ bf g_Ph[(size_t)B_ * S_ * S_], g_Pl[(size_t)B_ * S_ * S_];

// ---------------------------------------------------------------------------
// helpers
// ---------------------------------------------------------------------------
__device__ __forceinline__ uint32_t smem_u32(const void* p) {
    uint32_t a;
    asm("{ .reg .u64 t; cvta.to.shared.u64 t, %1; cvt.u32.u64 %0, t; }" : "=r"(a) : "l"(p));
    return a;
}
__device__ __forceinline__ void split2(float v, bf& h, bf& l) {
    h = __float2bfloat16(v);
    l = __float2bfloat16(v - __bfloat162float(h));
}
// swizzled byte offset within one 128x64B operand tile
__device__ __forceinline__ uint32_t sw_addr(uint32_t base, int row, int kc) {
    int off = row * 64 + kc * 16;
    return base + (uint32_t)(off ^ ((off >> 3) & 0x30));
}
__device__ __forceinline__ void ldsm_x4(uint32_t* r, uint32_t addr) {
    asm volatile("ldmatrix.sync.aligned.m8n8.x4.shared.b16 {%0,%1,%2,%3}, [%4];"
                 : "=r"(r[0]), "=r"(r[1]), "=r"(r[2]), "=r"(r[3]) : "r"(addr));
}
__device__ __forceinline__ void mma_bf16(float* c, const uint32_t* a, uint32_t b0, uint32_t b1) {
    asm volatile(
        "mma.sync.aligned.m16n8k16.row.col.f32.bf16.bf16.f32 "
        "{%0,%1,%2,%3}, {%4,%5,%6,%7}, {%8,%9}, {%0,%1,%2,%3};"
        : "+f"(c[0]), "+f"(c[1]), "+f"(c[2]), "+f"(c[3])
        : "r"(a[0]), "r"(a[1]), "r"(a[2]), "r"(a[3]), "r"(b0), "r"(b1));
}
// load one 128x32 bf16 operand tile (row-major, K-contig) into swizzled smem
__device__ __forceinline__ void load_oper(uint32_t sbase, const bf* __restrict__ g,
                                          int ld, int ko, int tid) {
#pragma unroll
    for (int j = 0; j < 2; j++) {
        int idx = tid + j * 256;
        int r = idx >> 2, c = idx & 3;
        uint32_t so = sw_addr(sbase, r, c);
        size_t ga = __cvta_generic_to_global(g + (size_t)r * ld + ko + c * 8);
        asm volatile("cp.async.cg.shared.global [%0], [%1], 16;" :: "r"(so), "l"(ga) : "memory");
    }
}

// ---------------------------------------------------------------------------
// bf16x3 NT GEMM via mma.sync: C[M,N] = A[M,K] * B[N,K]^T  (+bias/scale per MODE)
// MODE 0: +bias, write bf16 hi/lo row-major   (Q/K projections)
// MODE 1: +bias, write bf16 hi/lo transposed  (V projection -> Vt[b][d][s])
// MODE 2: *1/32, write fp32 row-major         (scores)
// MODE 3: write fp32 row-major                (PV -> output)
// ---------------------------------------------------------------------------
template<int MODE>
__global__ void __launch_bounds__(256, 1) mma_gemm(
    const bf* __restrict__ Ah, const bf* __restrict__ Al,
    const bf* __restrict__ Bh, const bf* __restrict__ Bl,
    const float* __restrict__ bias,
    float* __restrict__ Cf, bf* __restrict__ Ch, bf* __restrict__ Cl,
    int K, int lda, int ldb, int ldc,
    long long sA, long long sB, long long sC)
{
    extern __shared__ char smem[];
    const uint32_t sb0 = smem_u32(smem);
    const int tid = threadIdx.x;
    const int lane = tid & 31, wid = tid >> 5;
    const int warp_m = wid >> 2, warp_n = wid & 3;      // 2 x 4 warp grid
    const int bn = blockIdx.x, bm = blockIdx.y, bz = blockIdx.z;

    Ah += (size_t)bz * sA;  Al += (size_t)bz * sA;
    Bh += (size_t)bz * sB;  Bl += (size_t)bz * sB;

    const bf* pAh = Ah + (size_t)bm * 128 * lda;
    const bf* pAl = Al + (size_t)bm * 128 * lda;
    const bf* pBh = Bh + (size_t)bn * 128 * ldb;
    const bf* pBl = Bl + (size_t)bn * 128 * ldb;

    float acc[4][4][4];
#pragma unroll
    for (int i = 0; i < 4; i++)
#pragma unroll
        for (int j = 0; j < 4; j++)
#pragma unroll
            for (int q = 0; q < 4; q++) acc[i][j][q] = 0.0f;

    const int NK = K / KT;

    // prologue: stages 0, 1
#pragma unroll
    for (int s = 0; s < 2; s++) {
        uint32_t st = sb0 + s * STAGE_B;
        load_oper(st,              pAh, lda, s * KT, tid);
        load_oper(st + OPER_B,     pAl, lda, s * KT, tid);
        load_oper(st + 2 * OPER_B, pBh, ldb, s * KT, tid);
        load_oper(st + 3 * OPER_B, pBl, ldb, s * KT, tid);
        asm volatile("cp.async.commit_group;" ::: "memory");
    }

    // ldmatrix lane address components
    const int g8 = lane >> 3, lr = lane & 7;
    const int a_roff = ((g8 & 1) << 3) + lr;   // A: row add, kc add = g8>>1
    const int a_koff = g8 >> 1;
    const int b_roff = ((g8 >> 1) << 3) + lr;  // B: row add, kc add = g8&1
    const int b_koff = g8 & 1;

    for (int ks = 0; ks < NK; ks++) {
        if (ks + 1 < NK) asm volatile("cp.async.wait_group 1;" ::: "memory");
        else             asm volatile("cp.async.wait_group 0;" ::: "memory");
        __syncthreads();

        // prefetch stage ks+2 (buffer was fully consumed in iter ks-1; sync above protects)
        if (ks + 2 < NK) {
            uint32_t st = sb0 + ((ks + 2) % NSTAGE) * STAGE_B;
            int ko = (ks + 2) * KT;
            load_oper(st,              pAh, lda, ko, tid);
            load_oper(st + OPER_B,     pAl, lda, ko, tid);
            load_oper(st + 2 * OPER_B, pBh, ldb, ko, tid);
            load_oper(st + 3 * OPER_B, pBl, ldb, ko, tid);
            asm volatile("cp.async.commit_group;" ::: "memory");
        }

        const uint32_t st  = sb0 + (ks % NSTAGE) * STAGE_B;
        const uint32_t sAh = st, sAl = st + OPER_B, sBh = st + 2 * OPER_B, sBl = st + 3 * OPER_B;

#pragma unroll
        for (int kk = 0; kk < 2; kk++) {
            uint32_t ah[4][4], al[4][4], bh[2][4], bl[2][4];
#pragma unroll
            for (int mi = 0; mi < 4; mi++) {
                int row = warp_m * 64 + mi * 16 + a_roff;
                int kc  = kk * 2 + a_koff;
                ldsm_x4(ah[mi], sw_addr(sAh, row, kc));
                ldsm_x4(al[mi], sw_addr(sAl, row, kc));
            }
#pragma unroll
            for (int np = 0; np < 2; np++) {
                int row = warp_n * 32 + np * 16 + b_roff;
                int kc  = kk * 2 + b_koff;
                ldsm_x4(bh[np], sw_addr(sBh, row, kc));
                ldsm_x4(bl[np], sw_addr(sBl, row, kc));
            }
#pragma unroll
            for (int mi = 0; mi < 4; mi++)
#pragma unroll
                for (int nt = 0; nt < 4; nt++) {
                    const int np = nt >> 1, t = nt & 1;
                    mma_bf16(acc[mi][nt], ah[mi], bh[np][2 * t], bh[np][2 * t + 1]);  // hi*hi
                    mma_bf16(acc[mi][nt], ah[mi], bl[np][2 * t], bl[np][2 * t + 1]);  // hi*lo
                    mma_bf16(acc[mi][nt], al[mi], bh[np][2 * t], bh[np][2 * t + 1]);  // lo*hi
                }
        }
    }

    // ---------------- epilogue ----------------
#pragma unroll
    for (int mi = 0; mi < 4; mi++) {
#pragma unroll
        for (int h = 0; h < 2; h++) {
            const int grow = bm * 128 + warp_m * 64 + mi * 16 + h * 8 + (lane >> 2);
#pragma unroll
            for (int nt = 0; nt < 4; nt++) {
                const int col = bn * 128 + warp_n * 32 + (nt >> 1) * 16 + (nt & 1) * 8
                              + 2 * (lane & 3);
                float v0 = acc[mi][nt][2 * h];
                float v1 = acc[mi][nt][2 * h + 1];
                if constexpr (MODE == 0 || MODE == 1) {
                    v0 += bias[col]; v1 += bias[col + 1];
                    bf h0, l0, h1, l1;
                    split2(v0, h0, l0); split2(v1, h1, l1);
                    if constexpr (MODE == 0) {
                        __nv_bfloat162 hh(h0, h1), ll(l0, l1);
                        *reinterpret_cast<uint32_t*>(Ch + (size_t)grow * ldc + col) =
                            *reinterpret_cast<uint32_t*>(&hh);
                        *reinterpret_cast<uint32_t*>(Cl + (size_t)grow * ldc + col) =
                            *reinterpret_cast<uint32_t*>(&ll);
                    } else {
                        // transpose: Vt[batch][d=col][s]
                        const int batch = grow >> 11, s = grow & 2047;
                        const size_t idx = (size_t)batch * D_ * S_ + (size_t)col * S_ + s;
                        Ch[idx] = h0; Ch[idx + S_] = h1;
                        Cl[idx] = l0; Cl[idx + S_] = l1;
                    }
                } else {
                    const float scale = (MODE == 2) ? 0.03125f : 1.0f;
                    float2 o = make_float2(v0 * scale, v1 * scale);
                    *reinterpret_cast<float2*>(Cf + (size_t)bz * sC + (size_t)grow * ldc + col) = o;
                }
            }
        }
    }
}

// ---------------------------------------------------------------------------
// fp32 -> bf16 hi/lo split (elementwise)
// ---------------------------------------------------------------------------
__global__ void __launch_bounds__(256) split_kernel(
    const float* __restrict__ src, bf* __restrict__ h, bf* __restrict__ l, int n)
{
    int i = (blockIdx.x * 256 + threadIdx.x) * 4;
    if (i >= n) return;
    float4 v = *reinterpret_cast<const float4*>(src + i);
    bf h0, l0, h1, l1, h2, l2, h3, l3;
    split2(v.x, h0, l0); split2(v.y, h1, l1);
    split2(v.z, h2, l2); split2(v.w, h3, l3);
    __nv_bfloat162 ha(h0, h1), hb(h2, h3), la(l0, l1), lb(l2, l3);
    *reinterpret_cast<uint2*>(h + i) = make_uint2(*(uint32_t*)&ha, *(uint32_t*)&hb);
    *reinterpret_cast<uint2*>(l + i) = make_uint2(*(uint32_t*)&la, *(uint32_t*)&lb);
}

// ---------------------------------------------------------------------------
// masked softmax over each score row; emits P as bf16 hi/lo for PV GEMM
// ---------------------------------------------------------------------------
__global__ void __launch_bounds__(256) softmax_kernel(const int* __restrict__ mask)
{
    const int b = blockIdx.y, q = blockIdx.x, tid = threadIdx.x;
    const size_t rowoff = ((size_t)b * S_ + q) * S_;
    const float* row = g_S + rowoff;
    const int* m = mask + (size_t)b * S_;

    __shared__ float red[256];
    float v[8];
    float mx = -CUDART_INF_F;
#pragma unroll
    for (int i = 0; i < 8; i++) {
        int k = tid + i * 256;
        float s = row[k];
        v[i] = (m[k] != 0) ? s : -CUDART_INF_F;
        mx = fmaxf(mx, v[i]);
    }
    red[tid] = mx;
    __syncthreads();
    for (int s = 128; s > 0; s >>= 1) {
        if (tid < s) red[tid] = fmaxf(red[tid], red[tid + s]);
        __syncthreads();
    }
    mx = red[0];
    __syncthreads();

    float sum = 0.0f;
#pragma unroll
    for (int i = 0; i < 8; i++) {
        float e = __expf(v[i] - mx);
        v[i] = e;
        sum += e;
    }
    red[tid] = sum;
    __syncthreads();
    for (int s = 128; s > 0; s >>= 1) {
        if (tid < s) red[tid] += red[tid + s];
        __syncthreads();
    }
    const float inv = 1.0f / red[0];

#pragma unroll
    for (int i = 0; i < 8; i++) {
        int k = tid + i * 256;
        float p = v[i] * inv;
        bf h, l; split2(p, h, l);
        g_Ph[rowoff + k] = h;
        g_Pl[rowoff + k] = l;
    }
}

// ---------------------------------------------------------------------------
// Entry point (graph-capturable)
// ---------------------------------------------------------------------------
extern "C" void kernel_launch(void* const* d_in, const int* in_sizes, int n_in,
                              void* d_out, int out_size)
{
    const float* x    = (const float*)d_in[0];
    const int*   mask = (const int*)d_in[1];
    const float* Wq   = (const float*)d_in[2];
    const float* bq   = (const float*)d_in[3];
    const float* Wk   = (const float*)d_in[4];
    const float* bk   = (const float*)d_in[5];
    const float* Wv   = (const float*)d_in[6];
    const float* bv   = (const float*)d_in[7];
    float*       out  = (float*)d_out;

    cudaFuncSetAttribute(mma_gemm<0>, cudaFuncAttributeMaxDynamicSharedMemorySize, SMEM_TOTAL);
    cudaFuncSetAttribute(mma_gemm<1>, cudaFuncAttributeMaxDynamicSharedMemorySize, SMEM_TOTAL);
    cudaFuncSetAttribute(mma_gemm<2>, cudaFuncAttributeMaxDynamicSharedMemorySize, SMEM_TOTAL);
    cudaFuncSetAttribute(mma_gemm<3>, cudaFuncAttributeMaxDynamicSharedMemorySize, SMEM_TOTAL);

    void *xh, *xl, *Wh, *Wl, *Qh, *Ql, *Kh, *Kl, *Vth, *Vtl, *Sp, *Ph, *Pl;
    cudaGetSymbolAddress(&xh, g_xh);   cudaGetSymbolAddress(&xl, g_xl);
    cudaGetSymbolAddress(&Wh, g_Wh);   cudaGetSymbolAddress(&Wl, g_Wl);
    cudaGetSymbolAddress(&Qh, g_Qh);   cudaGetSymbolAddress(&Ql, g_Ql);
    cudaGetSymbolAddress(&Kh, g_Kh);   cudaGetSymbolAddress(&Kl, g_Kl);
    cudaGetSymbolAddress(&Vth, g_Vth); cudaGetSymbolAddress(&Vtl, g_Vtl);
    cudaGetSymbolAddress(&Sp, g_S);
    cudaGetSymbolAddress(&Ph, g_Ph);   cudaGetSymbolAddress(&Pl, g_Pl);

    bf *pxh = (bf*)xh, *pxl = (bf*)xl, *pWh = (bf*)Wh, *pWl = (bf*)Wl;
    bf *pQh = (bf*)Qh, *pQl = (bf*)Ql, *pKh = (bf*)Kh, *pKl = (bf*)Kl;
    bf *pVth = (bf*)Vth, *pVtl = (bf*)Vtl, *pPh = (bf*)Ph, *pPl = (bf*)Pl;
    float* pS = (float*)Sp;

    const int nx = MTOT * D_;   // 8,388,608
    const int nw = D_ * D_;     // 1,048,576

    split_kernel<<<nx / 1024, 256>>>(x,  pxh,          pxl,          nx);
    split_kernel<<<nw / 1024, 256>>>(Wq, pWh,          pWl,          nw);
    split_kernel<<<nw / 1024, 256>>>(Wk, pWh + nw,     pWl + nw,     nw);
    split_kernel<<<nw / 1024, 256>>>(Wv, pWh + 2 * nw, pWl + 2 * nw, nw);

    // Q, K projections: [8192,1024] = x @ W^T + b  -> bf16 hi/lo
    mma_gemm<0><<<dim3(8, 64, 1), 256, SMEM_TOTAL>>>(
        pxh, pxl, pWh, pWl, bq, nullptr, pQh, pQl, D_, D_, D_, D_, 0, 0, 0);
    mma_gemm<0><<<dim3(8, 64, 1), 256, SMEM_TOTAL>>>(
        pxh, pxl, pWh + nw, pWl + nw, bk, nullptr, pKh, pKl, D_, D_, D_, D_, 0, 0, 0);
    // V projection, written transposed as Vt[b][d][s]
    mma_gemm<1><<<dim3(8, 64, 1), 256, SMEM_TOTAL>>>(
        pxh, pxl, pWh + 2 * nw, pWl + 2 * nw, bv, nullptr, pVth, pVtl,
        D_, D_, D_, 0, 0, 0, 0);
    // scores = Q @ K^T / 32  (fp32)
    mma_gemm<2><<<dim3(16, 16, B_), 256, SMEM_TOTAL>>>(
        pQh, pQl, pKh, pKl, nullptr, pS, nullptr, nullptr,
        D_, D_, D_, S_, (long long)S_ * D_, (long long)S_ * D_, (long long)S_ * S_);
    // masked softmax -> P hi/lo
    softmax_kernel<<<dim3(S_, B_), 256>>>(mask);
    // out = P @ Vt^T (fp32 direct to d_out)
    mma_gemm<3><<<dim3(8, 16, B_), 256, SMEM_TOTAL>>>(
        pPh, pPl, pVth, pVtl, nullptr, out, nullptr, nullptr,
        S_, S_, S_, D_, (long long)S_ * S_, (long long)D_ * S_, (long long)S_ * D_);
}

// round 5
// speedup vs baseline: 2.7339x; 1.0279x over previous
#include <cuda_runtime.h>
#include <cuda_bf16.h>
#include <math_constants.h>
#include <cstdint>

// Problem shape: B=4, S=2048, D=1024
#define B_ 4
#define S_ 2048
#define D_ 1024
#define MTOT (B_ * S_)   // 8192

typedef __nv_bfloat16 bf;

// Tiling: CTA 128x128, Kt=32 bf16 per stage, 3 stages, 4 operands (Ah,Al,Bh,Bl)
#define KT 32
#define OPER_B 8192                       // 128 rows * 64B
#define STAGE_B (4 * OPER_B)              // 32KB
#define NSTAGE 3
#define SMEM_TOTAL (NSTAGE * STAGE_B)     // 98304

// ---------------------------------------------------------------------------
// Scratch (device globals — allocation-free)
// ---------------------------------------------------------------------------
__device__ bf g_xh[MTOT * D_], g_xl[MTOT * D_];
__device__ bf g_Wh[3][D_ * D_], g_Wl[3][D_ * D_];
__device__ float g_bias[3][D_];
__device__ bf g_Qh[MTOT * D_], g_Ql[MTOT * D_];
__device__ bf g_Kh[MTOT * D_], g_Kl[MTOT * D_];
__device__ bf g_Vth[(size_t)B_ * D_ * S_], g_Vtl[(size_t)B_ * D_ * S_];
__device__ float g_S[(size_t)B_ * S_ * S_];
__device__ bf g_Ph[(size_t)B_ * S_ * S_], g_Pl[(size_t)B_ * S_ * S_];

// ---------------------------------------------------------------------------
// helpers
// ---------------------------------------------------------------------------
__device__ __forceinline__ uint32_t smem_u32(const void* p) {
    uint32_t a;
    asm("{ .reg .u64 t; cvta.to.shared.u64 t, %1; cvt.u32.u64 %0, t; }" : "=r"(a) : "l"(p));
    return a;
}
__device__ __forceinline__ void split2(float v, bf& h, bf& l) {
    h = __float2bfloat16(v);
    l = __float2bfloat16(v - __bfloat162float(h));
}
// swizzled byte offset within one 128x64B operand tile
__device__ __forceinline__ uint32_t sw_addr(uint32_t base, int row, int kc) {
    int off = row * 64 + kc * 16;
    return base + (uint32_t)(off ^ ((off >> 3) & 0x30));
}
__device__ __forceinline__ void ldsm_x4(uint32_t* r, uint32_t addr) {
    asm volatile("ldmatrix.sync.aligned.m8n8.x4.shared.b16 {%0,%1,%2,%3}, [%4];"
                 : "=r"(r[0]), "=r"(r[1]), "=r"(r[2]), "=r"(r[3]) : "r"(addr));
}
__device__ __forceinline__ void mma_bf16(float* c, const uint32_t* a, uint32_t b0, uint32_t b1) {
    asm volatile(
        "mma.sync.aligned.m16n8k16.row.col.f32.bf16.bf16.f32 "
        "{%0,%1,%2,%3}, {%4,%5,%6,%7}, {%8,%9}, {%0,%1,%2,%3};"
        : "+f"(c[0]), "+f"(c[1]), "+f"(c[2]), "+f"(c[3])
        : "r"(a[0]), "r"(a[1]), "r"(a[2]), "r"(a[3]), "r"(b0), "r"(b1));
}
// load one 128x32 bf16 operand tile (row-major, K-contig) into swizzled smem
__device__ __forceinline__ void load_oper(uint32_t sbase, const bf* __restrict__ g,
                                          int ld, int ko, int tid) {
#pragma unroll
    for (int j = 0; j < 2; j++) {
        int idx = tid + j * 256;
        int r = idx >> 2, c = idx & 3;
        uint32_t so = sw_addr(sbase, r, c);
        size_t ga = __cvta_generic_to_global(g + (size_t)r * ld + ko + c * 8);
        asm volatile("cp.async.cg.shared.global [%0], [%1], 16;" :: "r"(so), "l"(ga) : "memory");
    }
}

// ---------------------------------------------------------------------------
// bf16x3 NT GEMM via mma.sync: C[M,N] = A[M,K] * B[N,K]^T
// MODE 0: fused QKV. grid.z selects W/bias/output (z=0: Q, z=1: K, z=2: V->Vt)
// MODE 2: *1/32, write fp32 row-major (scores)
// MODE 3: write fp32 row-major (PV -> output)
// Pass order is hi*hi (p0), hi*lo (p1), lo*hi (p2); MMAs interleaved across
// the 16 acc tiles so no back-to-back RAW on accumulator registers.
// ---------------------------------------------------------------------------
template<int MODE>
__global__ void __launch_bounds__(256, 1) mma_gemm(
    const bf* __restrict__ Ah, const bf* __restrict__ Al,
    const bf* __restrict__ Bh, const bf* __restrict__ Bl,
    float* __restrict__ Cf,
    int K, int lda, int ldb, int ldc,
    long long sA, long long sB, long long sC)
{
    extern __shared__ char smem[];
    const uint32_t sb0 = smem_u32(smem);
    const int tid = threadIdx.x;
    const int lane = tid & 31, wid = tid >> 5;
    const int warp_m = wid >> 2, warp_n = wid & 3;      // 2 x 4 warp grid
    const int bn = blockIdx.x, bm = blockIdx.y, bz = blockIdx.z;

    Ah += (size_t)bz * sA;  Al += (size_t)bz * sA;
    Bh += (size_t)bz * sB;  Bl += (size_t)bz * sB;

    const bf* pAh = Ah + (size_t)bm * 128 * lda;
    const bf* pAl = Al + (size_t)bm * 128 * lda;
    const bf* pBh = Bh + (size_t)bn * 128 * ldb;
    const bf* pBl = Bl + (size_t)bn * 128 * ldb;

    float acc[4][4][4];
#pragma unroll
    for (int i = 0; i < 4; i++)
#pragma unroll
        for (int j = 0; j < 4; j++)
#pragma unroll
            for (int q = 0; q < 4; q++) acc[i][j][q] = 0.0f;

    const int NK = K / KT;

    // prologue: stages 0, 1
#pragma unroll
    for (int s = 0; s < 2; s++) {
        uint32_t st = sb0 + s * STAGE_B;
        load_oper(st,              pAh, lda, s * KT, tid);
        load_oper(st + OPER_B,     pAl, lda, s * KT, tid);
        load_oper(st + 2 * OPER_B, pBh, ldb, s * KT, tid);
        load_oper(st + 3 * OPER_B, pBl, ldb, s * KT, tid);
        asm volatile("cp.async.commit_group;" ::: "memory");
    }

    // ldmatrix lane address components
    const int g8 = lane >> 3, lr = lane & 7;
    const int a_roff = ((g8 & 1) << 3) + lr;
    const int a_koff = g8 >> 1;
    const int b_roff = ((g8 >> 1) << 3) + lr;
    const int b_koff = g8 & 1;

    for (int ks = 0; ks < NK; ks++) {
        if (ks + 1 < NK) asm volatile("cp.async.wait_group 1;" ::: "memory");
        else             asm volatile("cp.async.wait_group 0;" ::: "memory");
        __syncthreads();

        // prefetch stage ks+2 (that buffer was consumed in iter ks-1; sync protects)
        if (ks + 2 < NK) {
            uint32_t st = sb0 + ((ks + 2) % NSTAGE) * STAGE_B;
            int ko = (ks + 2) * KT;
            load_oper(st,              pAh, lda, ko, tid);
            load_oper(st + OPER_B,     pAl, lda, ko, tid);
            load_oper(st + 2 * OPER_B, pBh, ldb, ko, tid);
            load_oper(st + 3 * OPER_B, pBl, ldb, ko, tid);
            asm volatile("cp.async.commit_group;" ::: "memory");
        }

        const uint32_t st  = sb0 + (ks % NSTAGE) * STAGE_B;
        const uint32_t sAh = st, sAl = st + OPER_B, sBh = st + 2 * OPER_B, sBl = st + 3 * OPER_B;

#pragma unroll
        for (int kk = 0; kk < 2; kk++) {
            uint32_t ah[4][4], al[4][4], bh[2][4], bl[2][4];
#pragma unroll
            for (int mi = 0; mi < 4; mi++) {
                int row = warp_m * 64 + mi * 16 + a_roff;
                int kc  = kk * 2 + a_koff;
                ldsm_x4(ah[mi], sw_addr(sAh, row, kc));
                ldsm_x4(al[mi], sw_addr(sAl, row, kc));
            }
#pragma unroll
            for (int np = 0; np < 2; np++) {
                int row = warp_n * 32 + np * 16 + b_roff;
                int kc  = kk * 2 + b_koff;
                ldsm_x4(bh[np], sw_addr(sBh, row, kc));
                ldsm_x4(bl[np], sw_addr(sBl, row, kc));
            }
            // pass-outer ordering: 16 independent accs between RAW reuse
#pragma unroll
            for (int p = 0; p < 3; p++)
#pragma unroll
                for (int mi = 0; mi < 4; mi++)
#pragma unroll
                    for (int nt = 0; nt < 4; nt++) {
                        const int np = nt >> 1, t = nt & 1;
                        const uint32_t* af = (p == 2) ? al[mi] : ah[mi];
                        const uint32_t* bp = (p == 1) ? bl[np] : bh[np];
                        mma_bf16(acc[mi][nt], af, bp[2 * t], bp[2 * t + 1]);
                    }
        }
    }

    // ---------------- epilogue ----------------
#pragma unroll
    for (int mi = 0; mi < 4; mi++) {
#pragma unroll
        for (int h = 0; h < 2; h++) {
            const int grow = bm * 128 + warp_m * 64 + mi * 16 + h * 8 + (lane >> 2);
#pragma unroll
            for (int nt = 0; nt < 4; nt++) {
                const int col = bn * 128 + warp_n * 32 + (nt >> 1) * 16 + (nt & 1) * 8
                              + 2 * (lane & 3);
                float v0 = acc[mi][nt][2 * h];
                float v1 = acc[mi][nt][2 * h + 1];
                if constexpr (MODE == 0) {
                    v0 += g_bias[bz][col]; v1 += g_bias[bz][col + 1];
                    bf h0, l0, h1, l1;
                    split2(v0, h0, l0); split2(v1, h1, l1);
                    if (bz == 0 || bz == 1) {
                        bf* dh = (bz == 0) ? g_Qh : g_Kh;
                        bf* dl = (bz == 0) ? g_Ql : g_Kl;
                        __nv_bfloat162 hh(h0, h1), ll(l0, l1);
                        *reinterpret_cast<uint32_t*>(dh + (size_t)grow * D_ + col) =
                            *reinterpret_cast<uint32_t*>(&hh);
                        *reinterpret_cast<uint32_t*>(dl + (size_t)grow * D_ + col) =
                            *reinterpret_cast<uint32_t*>(&ll);
                    } else {
                        // V: write transposed Vt[batch][d=col][s]
                        const int batch = grow >> 11, s = grow & 2047;
                        const size_t idx = (size_t)batch * D_ * S_ + (size_t)col * S_ + s;
                        g_Vth[idx] = h0; g_Vth[idx + S_] = h1;
                        g_Vtl[idx] = l0; g_Vtl[idx + S_] = l1;
                    }
                } else {
                    const float scale = (MODE == 2) ? 0.03125f : 1.0f;
                    float2 o = make_float2(v0 * scale, v1 * scale);
                    *reinterpret_cast<float2*>(Cf + (size_t)bz * sC + (size_t)grow * ldc + col) = o;
                }
            }
        }
    }
}

// ---------------------------------------------------------------------------
// fp32 -> bf16 hi/lo split (elementwise)
// ---------------------------------------------------------------------------
__global__ void __launch_bounds__(256) split_kernel(
    const float* __restrict__ src, bf* __restrict__ h, bf* __restrict__ l, int n)
{
    int i = (blockIdx.x * 256 + threadIdx.x) * 4;
    if (i >= n) return;
    float4 v = *reinterpret_cast<const float4*>(src + i);
    bf h0, l0, h1, l1, h2, l2, h3, l3;
    split2(v.x, h0, l0); split2(v.y, h1, l1);
    split2(v.z, h2, l2); split2(v.w, h3, l3);
    __nv_bfloat162 ha(h0, h1), hb(h2, h3), la(l0, l1), lb(l2, l3);
    *reinterpret_cast<uint2*>(h + i) = make_uint2(*(uint32_t*)&ha, *(uint32_t*)&hb);
    *reinterpret_cast<uint2*>(l + i) = make_uint2(*(uint32_t*)&la, *(uint32_t*)&lb);
}

// ---------------------------------------------------------------------------
// masked softmax over each score row; emits P as bf16 hi/lo for PV GEMM
// ---------------------------------------------------------------------------
__global__ void __launch_bounds__(256) softmax_kernel(const int* __restrict__ mask)
{
    const int b = blockIdx.y, q = blockIdx.x, tid = threadIdx.x;
    const size_t rowoff = ((size_t)b * S_ + q) * S_;
    const float* row = g_S + rowoff;
    const int* m = mask + (size_t)b * S_;

    __shared__ float red[256];
    float v[8];
    float mx = -CUDART_INF_F;
#pragma unroll
    for (int i = 0; i < 8; i++) {
        int k = tid + i * 256;
        float s = row[k];
        v[i] = (m[k] != 0) ? s : -CUDART_INF_F;
        mx = fmaxf(mx, v[i]);
    }
    red[tid] = mx;
    __syncthreads();
    for (int s = 128; s > 0; s >>= 1) {
        if (tid < s) red[tid] = fmaxf(red[tid], red[tid + s]);
        __syncthreads();
    }
    mx = red[0];
    __syncthreads();

    float sum = 0.0f;
#pragma unroll
    for (int i = 0; i < 8; i++) {
        float e = __expf(v[i] - mx);
        v[i] = e;
        sum += e;
    }
    red[tid] = sum;
    __syncthreads();
    for (int s = 128; s > 0; s >>= 1) {
        if (tid < s) red[tid] += red[tid + s];
        __syncthreads();
    }
    const float inv = 1.0f / red[0];

#pragma unroll
    for (int i = 0; i < 8; i++) {
        int k = tid + i * 256;
        float p = v[i] * inv;
        bf h, l; split2(p, h, l);
        g_Ph[rowoff + k] = h;
        g_Pl[rowoff + k] = l;
    }
}

// ---------------------------------------------------------------------------
// Entry point (graph-capturable)
// ---------------------------------------------------------------------------
extern "C" void kernel_launch(void* const* d_in, const int* in_sizes, int n_in,
                              void* d_out, int out_size)
{
    const float* x    = (const float*)d_in[0];
    const int*   mask = (const int*)d_in[1];
    const float* Wq   = (const float*)d_in[2];
    const float* bq   = (const float*)d_in[3];
    const float* Wk   = (const float*)d_in[4];
    const float* bk   = (const float*)d_in[5];
    const float* Wv   = (const float*)d_in[6];
    const float* bv   = (const float*)d_in[7];
    float*       out  = (float*)d_out;

    cudaFuncSetAttribute(mma_gemm<0>, cudaFuncAttributeMaxDynamicSharedMemorySize, SMEM_TOTAL);
    cudaFuncSetAttribute(mma_gemm<2>, cudaFuncAttributeMaxDynamicSharedMemorySize, SMEM_TOTAL);
    cudaFuncSetAttribute(mma_gemm<3>, cudaFuncAttributeMaxDynamicSharedMemorySize, SMEM_TOTAL);

    void *xh, *xl, *Wh, *Wl, *Qh, *Ql, *Kh, *Kl, *Vth, *Vtl, *Sp, *Ph, *Pl, *bias;
    cudaGetSymbolAddress(&xh, g_xh);   cudaGetSymbolAddress(&xl, g_xl);
    cudaGetSymbolAddress(&Wh, g_Wh);   cudaGetSymbolAddress(&Wl, g_Wl);
    cudaGetSymbolAddress(&Qh, g_Qh);   cudaGetSymbolAddress(&Ql, g_Ql);
    cudaGetSymbolAddress(&Kh, g_Kh);   cudaGetSymbolAddress(&Kl, g_Kl);
    cudaGetSymbolAddress(&Vth, g_Vth); cudaGetSymbolAddress(&Vtl, g_Vtl);
    cudaGetSymbolAddress(&Sp, g_S);
    cudaGetSymbolAddress(&Ph, g_Ph);   cudaGetSymbolAddress(&Pl, g_Pl);
    cudaGetSymbolAddress(&bias, g_bias);

    bf *pxh = (bf*)xh, *pxl = (bf*)xl, *pWh = (bf*)Wh, *pWl = (bf*)Wl;
    bf *pQh = (bf*)Qh, *pQl = (bf*)Ql, *pKh = (bf*)Kh, *pKl = (bf*)Kl;
    bf *pVth = (bf*)Vth, *pVtl = (bf*)Vtl, *pPh = (bf*)Ph, *pPl = (bf*)Pl;
    float* pS = (float*)Sp;
    float* pBias = (float*)bias;

    const int nx = MTOT * D_;   // 8,388,608
    const int nw = D_ * D_;     // 1,048,576

    // stage biases into g_bias (capturable D2D copies)
    cudaMemcpyAsync(pBias,          bq, D_ * sizeof(float), cudaMemcpyDeviceToDevice);
    cudaMemcpyAsync(pBias + D_,     bk, D_ * sizeof(float), cudaMemcpyDeviceToDevice);
    cudaMemcpyAsync(pBias + 2 * D_, bv, D_ * sizeof(float), cudaMemcpyDeviceToDevice);

    split_kernel<<<nx / 1024, 256>>>(x,  pxh,          pxl,          nx);
    split_kernel<<<nw / 1024, 256>>>(Wq, pWh,          pWl,          nw);
    split_kernel<<<nw / 1024, 256>>>(Wk, pWh + nw,     pWl + nw,     nw);
    split_kernel<<<nw / 1024, 256>>>(Wv, pWh + 2 * nw, pWl + 2 * nw, nw);

    // fused QKV projections: z selects weight/bias/output
    mma_gemm<0><<<dim3(8, 64, 3), 256, SMEM_TOTAL>>>(
        pxh, pxl, pWh, pWl, nullptr, D_, D_, D_, D_, 0, (long long)nw, 0);
    // scores = Q @ K^T / 32  (fp32)
    mma_gemm<2><<<dim3(16, 16, B_), 256, SMEM_TOTAL>>>(
        pQh, pQl, pKh, pKl, pS,
        D_, D_, D_, S_, (long long)S_ * D_, (long long)S_ * D_, (long long)S_ * S_);
    // masked softmax -> P hi/lo
    softmax_kernel<<<dim3(S_, B_), 256>>>(mask);
    // out = P @ Vt^T (fp32 direct to d_out)
    mma_gemm<3><<<dim3(8, 16, B_), 256, SMEM_TOTAL>>>(
        pPh, pPl, pVth, pVtl, out,
        S_, S_, S_, D_, (long long)S_ * S_, (long long)D_ * S_, (long long)S_ * D_);
}

// round 6
// speedup vs baseline: 4.4227x; 1.6177x over previous
#include <cuda_runtime.h>
#include <cuda_bf16.h>
#include <cuda_fp16.h>
#include <math_constants.h>
#include <cstdint>

// Problem shape: B=4, S=2048, D=1024
#define B_ 4
#define S_ 2048
#define D_ 1024
#define MTOT (B_ * S_)   // 8192

typedef __nv_bfloat16 bf;

// Tiling: CTA 128x128, Kt=32 (16-bit elems) per stage, 3 stages
#define KT 32
#define OPER_B 8192                        // 128 rows * 64B
#define NSTAGE 3
// QKV kernel: 4 operands (Ah,Al,Bh,Bl) per stage
#define STAGE4_B (4 * OPER_B)
#define SMEM_QKV (NSTAGE * STAGE4_B)       // 98304
// fp16 single-pass kernel: 2 operands per stage
#define STAGE2_B (2 * OPER_B)
#define SMEM_F16 (NSTAGE * STAGE2_B)       // 49152

// ---------------------------------------------------------------------------
// Scratch (device globals — allocation-free)
// ---------------------------------------------------------------------------
__device__ bf g_xh[MTOT * D_], g_xl[MTOT * D_];
__device__ bf g_Wh[3][D_ * D_], g_Wl[3][D_ * D_];
__device__ float g_bias[3][D_];
__device__ __half g_Qf[MTOT * D_];                    // fp16 Q
__device__ __half g_Kf[MTOT * D_];                    // fp16 K
__device__ __half g_Vtf[(size_t)B_ * D_ * S_];        // fp16 V transposed [b][d][s]
__device__ float  g_S[(size_t)B_ * S_ * S_];          // fp32 scores
__device__ __half g_Pf[(size_t)B_ * S_ * S_];         // fp16 probs

// ---------------------------------------------------------------------------
// helpers
// ---------------------------------------------------------------------------
__device__ __forceinline__ uint32_t smem_u32(const void* p) {
    uint32_t a;
    asm("{ .reg .u64 t; cvta.to.shared.u64 t, %1; cvt.u32.u64 %0, t; }" : "=r"(a) : "l"(p));
    return a;
}
__device__ __forceinline__ void split2(float v, bf& h, bf& l) {
    h = __float2bfloat16(v);
    l = __float2bfloat16(v - __bfloat162float(h));
}
// swizzled byte offset within one 128x64B operand tile
__device__ __forceinline__ uint32_t sw_addr(uint32_t base, int row, int kc) {
    int off = row * 64 + kc * 16;
    return base + (uint32_t)(off ^ ((off >> 3) & 0x30));
}
__device__ __forceinline__ void ldsm_x4(uint32_t* r, uint32_t addr) {
    asm volatile("ldmatrix.sync.aligned.m8n8.x4.shared.b16 {%0,%1,%2,%3}, [%4];"
                 : "=r"(r[0]), "=r"(r[1]), "=r"(r[2]), "=r"(r[3]) : "r"(addr));
}
__device__ __forceinline__ void mma_bf16(float* c, const uint32_t* a, uint32_t b0, uint32_t b1) {
    asm volatile(
        "mma.sync.aligned.m16n8k16.row.col.f32.bf16.bf16.f32 "
        "{%0,%1,%2,%3}, {%4,%5,%6,%7}, {%8,%9}, {%0,%1,%2,%3};"
        : "+f"(c[0]), "+f"(c[1]), "+f"(c[2]), "+f"(c[3])
        : "r"(a[0]), "r"(a[1]), "r"(a[2]), "r"(a[3]), "r"(b0), "r"(b1));
}
__device__ __forceinline__ void mma_f16(float* c, const uint32_t* a, uint32_t b0, uint32_t b1) {
    asm volatile(
        "mma.sync.aligned.m16n8k16.row.col.f32.f16.f16.f32 "
        "{%0,%1,%2,%3}, {%4,%5,%6,%7}, {%8,%9}, {%0,%1,%2,%3};"
        : "+f"(c[0]), "+f"(c[1]), "+f"(c[2]), "+f"(c[3])
        : "r"(a[0]), "r"(a[1]), "r"(a[2]), "r"(a[3]), "r"(b0), "r"(b1));
}
// load one 128x32 16-bit operand tile (row-major, K-contig) into swizzled smem
template<typename T>
__device__ __forceinline__ void load_oper(uint32_t sbase, const T* __restrict__ g,
                                          int ld, int ko, int tid) {
#pragma unroll
    for (int j = 0; j < 2; j++) {
        int idx = tid + j * 256;
        int r = idx >> 2, c = idx & 3;
        uint32_t so = sw_addr(sbase, r, c);
        size_t ga = __cvta_generic_to_global(g + (size_t)r * ld + ko + c * 8);
        asm volatile("cp.async.cg.shared.global [%0], [%1], 16;" :: "r"(so), "l"(ga) : "memory");
    }
}

// ---------------------------------------------------------------------------
// QKV projection: bf16x3 NT GEMM, fused over grid.z (0:Q, 1:K, 2:V->Vt),
// epilogue adds bias and writes fp16.
// ---------------------------------------------------------------------------
__global__ void __launch_bounds__(256, 1) qkv_gemm(
    const bf* __restrict__ Ah, const bf* __restrict__ Al,
    const bf* __restrict__ Bh, const bf* __restrict__ Bl)
{
    extern __shared__ char smem[];
    const uint32_t sb0 = smem_u32(smem);
    const int tid = threadIdx.x;
    const int lane = tid & 31, wid = tid >> 5;
    const int warp_m = wid >> 2, warp_n = wid & 3;
    const int bn = blockIdx.x, bm = blockIdx.y, bz = blockIdx.z;

    Bh += (size_t)bz * (D_ * D_);
    Bl += (size_t)bz * (D_ * D_);

    const bf* pAh = Ah + (size_t)bm * 128 * D_;
    const bf* pAl = Al + (size_t)bm * 128 * D_;
    const bf* pBh = Bh + (size_t)bn * 128 * D_;
    const bf* pBl = Bl + (size_t)bn * 128 * D_;

    float acc[4][4][4];
#pragma unroll
    for (int i = 0; i < 4; i++)
#pragma unroll
        for (int j = 0; j < 4; j++)
#pragma unroll
            for (int q = 0; q < 4; q++) acc[i][j][q] = 0.0f;

    const int NK = D_ / KT;

#pragma unroll
    for (int s = 0; s < 2; s++) {
        uint32_t st = sb0 + s * STAGE4_B;
        load_oper(st,              pAh, D_, s * KT, tid);
        load_oper(st + OPER_B,     pAl, D_, s * KT, tid);
        load_oper(st + 2 * OPER_B, pBh, D_, s * KT, tid);
        load_oper(st + 3 * OPER_B, pBl, D_, s * KT, tid);
        asm volatile("cp.async.commit_group;" ::: "memory");
    }

    const int g8 = lane >> 3, lr = lane & 7;
    const int a_roff = ((g8 & 1) << 3) + lr, a_koff = g8 >> 1;
    const int b_roff = ((g8 >> 1) << 3) + lr, b_koff = g8 & 1;

    for (int ks = 0; ks < NK; ks++) {
        if (ks + 1 < NK) asm volatile("cp.async.wait_group 1;" ::: "memory");
        else             asm volatile("cp.async.wait_group 0;" ::: "memory");
        __syncthreads();

        if (ks + 2 < NK) {
            uint32_t st = sb0 + ((ks + 2) % NSTAGE) * STAGE4_B;
            int ko = (ks + 2) * KT;
            load_oper(st,              pAh, D_, ko, tid);
            load_oper(st + OPER_B,     pAl, D_, ko, tid);
            load_oper(st + 2 * OPER_B, pBh, D_, ko, tid);
            load_oper(st + 3 * OPER_B, pBl, D_, ko, tid);
            asm volatile("cp.async.commit_group;" ::: "memory");
        }

        const uint32_t st  = sb0 + (ks % NSTAGE) * STAGE4_B;
        const uint32_t sAh = st, sAl = st + OPER_B, sBh = st + 2 * OPER_B, sBl = st + 3 * OPER_B;

#pragma unroll
        for (int kk = 0; kk < 2; kk++) {
            uint32_t ah[4][4], al[4][4], bh[2][4], bl[2][4];
#pragma unroll
            for (int mi = 0; mi < 4; mi++) {
                int row = warp_m * 64 + mi * 16 + a_roff;
                int kc  = kk * 2 + a_koff;
                ldsm_x4(ah[mi], sw_addr(sAh, row, kc));
                ldsm_x4(al[mi], sw_addr(sAl, row, kc));
            }
#pragma unroll
            for (int np = 0; np < 2; np++) {
                int row = warp_n * 32 + np * 16 + b_roff;
                int kc  = kk * 2 + b_koff;
                ldsm_x4(bh[np], sw_addr(sBh, row, kc));
                ldsm_x4(bl[np], sw_addr(sBl, row, kc));
            }
#pragma unroll
            for (int p = 0; p < 3; p++)
#pragma unroll
                for (int mi = 0; mi < 4; mi++)
#pragma unroll
                    for (int nt = 0; nt < 4; nt++) {
                        const int np = nt >> 1, t = nt & 1;
                        const uint32_t* af = (p == 2) ? al[mi] : ah[mi];
                        const uint32_t* bp = (p == 1) ? bl[np] : bh[np];
                        mma_bf16(acc[mi][nt], af, bp[2 * t], bp[2 * t + 1]);
                    }
        }
    }

    // epilogue: +bias, fp16 outputs
#pragma unroll
    for (int mi = 0; mi < 4; mi++) {
#pragma unroll
        for (int h = 0; h < 2; h++) {
            const int grow = bm * 128 + warp_m * 64 + mi * 16 + h * 8 + (lane >> 2);
#pragma unroll
            for (int nt = 0; nt < 4; nt++) {
                const int col = bn * 128 + warp_n * 32 + (nt >> 1) * 16 + (nt & 1) * 8
                              + 2 * (lane & 3);
                float v0 = acc[mi][nt][2 * h] + g_bias[bz][col];
                float v1 = acc[mi][nt][2 * h + 1] + g_bias[bz][col + 1];
                if (bz == 2) {
                    // Vt[batch][d=col][s]
                    const int batch = grow >> 11, s = grow & 2047;
                    const size_t idx = (size_t)batch * D_ * S_ + (size_t)col * S_ + s;
                    g_Vtf[idx]      = __float2half_rn(v0);
                    g_Vtf[idx + S_] = __float2half_rn(v1);
                } else {
                    __half* dst = (bz == 0) ? g_Qf : g_Kf;
                    __half2 o = __floats2half2_rn(v0, v1);
                    *reinterpret_cast<__half2*>(dst + (size_t)grow * D_ + col) = o;
                }
            }
        }
    }
}

// ---------------------------------------------------------------------------
// Single-pass fp16 NT GEMM: C[M,N] = A[M,K] * B[N,K]^T
// MODE 2: *1/32 -> fp32 scores; MODE 3: -> fp32 output
// ---------------------------------------------------------------------------
template<int MODE>
__global__ void __launch_bounds__(256) f16_gemm(
    const __half* __restrict__ A, const __half* __restrict__ B,
    float* __restrict__ Cf,
    int K, int ldc, long long sA, long long sB, long long sC)
{
    extern __shared__ char smem[];
    const uint32_t sb0 = smem_u32(smem);
    const int tid = threadIdx.x;
    const int lane = tid & 31, wid = tid >> 5;
    const int warp_m = wid >> 2, warp_n = wid & 3;
    const int bn = blockIdx.x, bm = blockIdx.y, bz = blockIdx.z;

    const __half* pA = A + (size_t)bz * sA + (size_t)bm * 128 * K;
    const __half* pB = B + (size_t)bz * sB + (size_t)bn * 128 * K;

    float acc[4][4][4];
#pragma unroll
    for (int i = 0; i < 4; i++)
#pragma unroll
        for (int j = 0; j < 4; j++)
#pragma unroll
            for (int q = 0; q < 4; q++) acc[i][j][q] = 0.0f;

    const int NK = K / KT;

#pragma unroll
    for (int s = 0; s < 2; s++) {
        uint32_t st = sb0 + s * STAGE2_B;
        load_oper(st,          pA, K, s * KT, tid);
        load_oper(st + OPER_B, pB, K, s * KT, tid);
        asm volatile("cp.async.commit_group;" ::: "memory");
    }

    const int g8 = lane >> 3, lr = lane & 7;
    const int a_roff = ((g8 & 1) << 3) + lr, a_koff = g8 >> 1;
    const int b_roff = ((g8 >> 1) << 3) + lr, b_koff = g8 & 1;

    for (int ks = 0; ks < NK; ks++) {
        if (ks + 1 < NK) asm volatile("cp.async.wait_group 1;" ::: "memory");
        else             asm volatile("cp.async.wait_group 0;" ::: "memory");
        __syncthreads();

        if (ks + 2 < NK) {
            uint32_t st = sb0 + ((ks + 2) % NSTAGE) * STAGE2_B;
            int ko = (ks + 2) * KT;
            load_oper(st,          pA, K, ko, tid);
            load_oper(st + OPER_B, pB, K, ko, tid);
            asm volatile("cp.async.commit_group;" ::: "memory");
        }

        const uint32_t st = sb0 + (ks % NSTAGE) * STAGE2_B;
        const uint32_t sA_ = st, sB_ = st + OPER_B;

#pragma unroll
        for (int kk = 0; kk < 2; kk++) {
            uint32_t a[4][4], b[2][4];
#pragma unroll
            for (int mi = 0; mi < 4; mi++) {
                int row = warp_m * 64 + mi * 16 + a_roff;
                ldsm_x4(a[mi], sw_addr(sA_, row, kk * 2 + a_koff));
            }
#pragma unroll
            for (int np = 0; np < 2; np++) {
                int row = warp_n * 32 + np * 16 + b_roff;
                ldsm_x4(b[np], sw_addr(sB_, row, kk * 2 + b_koff));
            }
#pragma unroll
            for (int mi = 0; mi < 4; mi++)
#pragma unroll
                for (int nt = 0; nt < 4; nt++) {
                    const int np = nt >> 1, t = nt & 1;
                    mma_f16(acc[mi][nt], a[mi], b[np][2 * t], b[np][2 * t + 1]);
                }
        }
    }

    const float scale = (MODE == 2) ? 0.03125f : 1.0f;
#pragma unroll
    for (int mi = 0; mi < 4; mi++) {
#pragma unroll
        for (int h = 0; h < 2; h++) {
            const int grow = bm * 128 + warp_m * 64 + mi * 16 + h * 8 + (lane >> 2);
#pragma unroll
            for (int nt = 0; nt < 4; nt++) {
                const int col = bn * 128 + warp_n * 32 + (nt >> 1) * 16 + (nt & 1) * 8
                              + 2 * (lane & 3);
                float2 o = make_float2(acc[mi][nt][2 * h] * scale,
                                       acc[mi][nt][2 * h + 1] * scale);
                *reinterpret_cast<float2*>(Cf + (size_t)bz * sC + (size_t)grow * ldc + col) = o;
            }
        }
    }
}

// ---------------------------------------------------------------------------
// fp32 -> bf16 hi/lo split (elementwise)
// ---------------------------------------------------------------------------
__global__ void __launch_bounds__(256) split_kernel(
    const float* __restrict__ src, bf* __restrict__ h, bf* __restrict__ l, int n)
{
    int i = (blockIdx.x * 256 + threadIdx.x) * 4;
    if (i >= n) return;
    float4 v = *reinterpret_cast<const float4*>(src + i);
    bf h0, l0, h1, l1, h2, l2, h3, l3;
    split2(v.x, h0, l0); split2(v.y, h1, l1);
    split2(v.z, h2, l2); split2(v.w, h3, l3);
    __nv_bfloat162 ha(h0, h1), hb(h2, h3), la(l0, l1), lb(l2, l3);
    *reinterpret_cast<uint2*>(h + i) = make_uint2(*(uint32_t*)&ha, *(uint32_t*)&hb);
    *reinterpret_cast<uint2*>(l + i) = make_uint2(*(uint32_t*)&la, *(uint32_t*)&lb);
}

// ---------------------------------------------------------------------------
// masked softmax over each score row; emits P as fp16
// ---------------------------------------------------------------------------
__global__ void __launch_bounds__(256) softmax_kernel(const int* __restrict__ mask)
{
    const int b = blockIdx.y, q = blockIdx.x, tid = threadIdx.x;
    const size_t rowoff = ((size_t)b * S_ + q) * S_;
    const float* row = g_S + rowoff;
    const int* m = mask + (size_t)b * S_;

    __shared__ float red[256];
    float v[8];
    float mx = -CUDART_INF_F;
#pragma unroll
    for (int i = 0; i < 8; i++) {
        int k = tid + i * 256;
        float s = row[k];
        v[i] = (m[k] != 0) ? s : -CUDART_INF_F;
        mx = fmaxf(mx, v[i]);
    }
    red[tid] = mx;
    __syncthreads();
    for (int s = 128; s > 0; s >>= 1) {
        if (tid < s) red[tid] = fmaxf(red[tid], red[tid + s]);
        __syncthreads();
    }
    mx = red[0];
    __syncthreads();

    float sum = 0.0f;
#pragma unroll
    for (int i = 0; i < 8; i++) {
        float e = __expf(v[i] - mx);
        v[i] = e;
        sum += e;
    }
    red[tid] = sum;
    __syncthreads();
    for (int s = 128; s > 0; s >>= 1) {
        if (tid < s) red[tid] += red[tid + s];
        __syncthreads();
    }
    const float inv = 1.0f / red[0];

#pragma unroll
    for (int i = 0; i < 8; i++) {
        int k = tid + i * 256;
        g_Pf[rowoff + k] = __float2half_rn(v[i] * inv);
    }
}

// ---------------------------------------------------------------------------
// Entry point (graph-capturable)
// ---------------------------------------------------------------------------
extern "C" void kernel_launch(void* const* d_in, const int* in_sizes, int n_in,
                              void* d_out, int out_size)
{
    const float* x    = (const float*)d_in[0];
    const int*   mask = (const int*)d_in[1];
    const float* Wq   = (const float*)d_in[2];
    const float* bq   = (const float*)d_in[3];
    const float* Wk   = (const float*)d_in[4];
    const float* bk   = (const float*)d_in[5];
    const float* Wv   = (const float*)d_in[6];
    const float* bv   = (const float*)d_in[7];
    float*       out  = (float*)d_out;

    cudaFuncSetAttribute(qkv_gemm,   cudaFuncAttributeMaxDynamicSharedMemorySize, SMEM_QKV);
    cudaFuncSetAttribute(f16_gemm<2>, cudaFuncAttributeMaxDynamicSharedMemorySize, SMEM_F16);
    cudaFuncSetAttribute(f16_gemm<3>, cudaFuncAttributeMaxDynamicSharedMemorySize, SMEM_F16);

    void *xh, *xl, *Wh, *Wl, *Qf, *Kf, *Vtf, *Sp, *Pf, *bias;
    cudaGetSymbolAddress(&xh, g_xh);   cudaGetSymbolAddress(&xl, g_xl);
    cudaGetSymbolAddress(&Wh, g_Wh);   cudaGetSymbolAddress(&Wl, g_Wl);
    cudaGetSymbolAddress(&Qf, g_Qf);   cudaGetSymbolAddress(&Kf, g_Kf);
    cudaGetSymbolAddress(&Vtf, g_Vtf); cudaGetSymbolAddress(&Sp, g_S);
    cudaGetSymbolAddress(&Pf, g_Pf);   cudaGetSymbolAddress(&bias, g_bias);

    bf *pxh = (bf*)xh, *pxl = (bf*)xl, *pWh = (bf*)Wh, *pWl = (bf*)Wl;
    __half *pQf = (__half*)Qf, *pKf = (__half*)Kf, *pVtf = (__half*)Vtf, *pPf = (__half*)Pf;
    float* pS = (float*)Sp;
    float* pBias = (float*)bias;

    const int nx = MTOT * D_;
    const int nw = D_ * D_;

    cudaMemcpyAsync(pBias,          bq, D_ * sizeof(float), cudaMemcpyDeviceToDevice);
    cudaMemcpyAsync(pBias + D_,     bk, D_ * sizeof(float), cudaMemcpyDeviceToDevice);
    cudaMemcpyAsync(pBias + 2 * D_, bv, D_ * sizeof(float), cudaMemcpyDeviceToDevice);

    split_kernel<<<nx / 1024, 256>>>(x,  pxh,          pxl,          nx);
    split_kernel<<<nw / 1024, 256>>>(Wq, pWh,          pWl,          nw);
    split_kernel<<<nw / 1024, 256>>>(Wk, pWh + nw,     pWl + nw,     nw);
    split_kernel<<<nw / 1024, 256>>>(Wv, pWh + 2 * nw, pWl + 2 * nw, nw);

    // fused QKV projections (bf16x3 -> fp16 Q, K, Vt)
    qkv_gemm<<<dim3(8, 64, 3), 256, SMEM_QKV>>>(pxh, pxl, pWh, pWl);
    // scores = Q @ K^T / 32 (fp16 single-pass, fp32 out)
    f16_gemm<2><<<dim3(16, 16, B_), 256, SMEM_F16>>>(
        pQf, pKf, pS, D_, S_,
        (long long)S_ * D_, (long long)S_ * D_, (long long)S_ * S_);
    // masked softmax -> P fp16
    softmax_kernel<<<dim3(S_, B_), 256>>>(mask);
    // out = P @ Vt^T (fp16 single-pass, fp32 direct to d_out)
    f16_gemm<3><<<dim3(8, 16, B_), 256, SMEM_F16>>>(
        pPf, pVtf, out, S_, D_,
        (long long)S_ * S_, (long long)D_ * S_, (long long)S_ * D_);
}

// round 7
// speedup vs baseline: 7.9310x; 1.7933x over previous
#include <cuda_runtime.h>
#include <cuda_fp16.h>
#include <math_constants.h>
#include <cstdint>

// Problem shape: B=4, S=2048, D=1024
#define B_ 4
#define S_ 2048
#define D_ 1024
#define MTOT (B_ * S_)   // 8192

// Tiling: CTA 128x128, Kt=32 fp16 per stage, 3 stages, 2 operands
#define KT 32
#define OPER_B 8192                        // 128 rows * 64B
#define NSTAGE 3
#define STAGE_B (2 * OPER_B)
#define SMEM_GEMM (NSTAGE * STAGE_B)       // 49152

// ---------------------------------------------------------------------------
// Scratch (device globals — allocation-free)
// ---------------------------------------------------------------------------
__device__ __half g_xf[MTOT * D_];                    // fp16 x
__device__ __half g_Wf[3][D_ * D_];                   // fp16 Wq/Wk/Wv
__device__ float  g_bias[3][D_];
__device__ __half g_Qf[MTOT * D_];                    // fp16 Q
__device__ __half g_Kf[MTOT * D_];                    // fp16 K
__device__ __half g_Vtf[(size_t)B_ * D_ * S_];        // fp16 V transposed [b][d][s]
__device__ float  g_S[(size_t)B_ * S_ * S_];          // fp32 scores
__device__ __half g_Pf[(size_t)B_ * S_ * S_];         // fp16 probs

// ---------------------------------------------------------------------------
// helpers
// ---------------------------------------------------------------------------
__device__ __forceinline__ uint32_t smem_u32(const void* p) {
    uint32_t a;
    asm("{ .reg .u64 t; cvta.to.shared.u64 t, %1; cvt.u32.u64 %0, t; }" : "=r"(a) : "l"(p));
    return a;
}
// swizzled byte offset within one 128x64B operand tile
__device__ __forceinline__ uint32_t sw_addr(uint32_t base, int row, int kc) {
    int off = row * 64 + kc * 16;
    return base + (uint32_t)(off ^ ((off >> 3) & 0x30));
}
__device__ __forceinline__ void ldsm_x4(uint32_t* r, uint32_t addr) {
    asm volatile("ldmatrix.sync.aligned.m8n8.x4.shared.b16 {%0,%1,%2,%3}, [%4];"
                 : "=r"(r[0]), "=r"(r[1]), "=r"(r[2]), "=r"(r[3]) : "r"(addr));
}
__device__ __forceinline__ void mma_f16(float* c, const uint32_t* a, uint32_t b0, uint32_t b1) {
    asm volatile(
        "mma.sync.aligned.m16n8k16.row.col.f32.f16.f16.f32 "
        "{%0,%1,%2,%3}, {%4,%5,%6,%7}, {%8,%9}, {%0,%1,%2,%3};"
        : "+f"(c[0]), "+f"(c[1]), "+f"(c[2]), "+f"(c[3])
        : "r"(a[0]), "r"(a[1]), "r"(a[2]), "r"(a[3]), "r"(b0), "r"(b1));
}
// load one 128x32 fp16 operand tile (row-major, K-contig) into swizzled smem
__device__ __forceinline__ void load_oper(uint32_t sbase, const __half* __restrict__ g,
                                          int ld, int ko, int tid) {
#pragma unroll
    for (int j = 0; j < 2; j++) {
        int idx = tid + j * 256;
        int r = idx >> 2, c = idx & 3;
        uint32_t so = sw_addr(sbase, r, c);
        size_t ga = __cvta_generic_to_global(g + (size_t)r * ld + ko + c * 8);
        asm volatile("cp.async.cg.shared.global [%0], [%1], 16;" :: "r"(so), "l"(ga) : "memory");
    }
}

// ---------------------------------------------------------------------------
// Single-pass fp16 NT GEMM: C[M,N] = A[M,K] * B[N,K]^T
// MODE 0: QKV projection. grid.z selects W/bias/output (0:Q, 1:K, 2:V->Vt);
//         epilogue adds bias, writes fp16.
// MODE 2: *1/32 -> fp32 scores
// MODE 3: -> fp32 output
// ---------------------------------------------------------------------------
template<int MODE>
__global__ void __launch_bounds__(256) f16_gemm(
    const __half* __restrict__ A, const __half* __restrict__ B,
    float* __restrict__ Cf,
    int K, int ldc, long long sA, long long sB, long long sC)
{
    extern __shared__ char smem[];
    const uint32_t sb0 = smem_u32(smem);
    const int tid = threadIdx.x;
    const int lane = tid & 31, wid = tid >> 5;
    const int warp_m = wid >> 2, warp_n = wid & 3;     // 2 x 4 warp grid
    const int bn = blockIdx.x, bm = blockIdx.y, bz = blockIdx.z;

    const __half* pA = A + (size_t)bz * sA + (size_t)bm * 128 * K;
    const __half* pB = B + (size_t)bz * sB + (size_t)bn * 128 * K;

    float acc[4][4][4];
#pragma unroll
    for (int i = 0; i < 4; i++)
#pragma unroll
        for (int j = 0; j < 4; j++)
#pragma unroll
            for (int q = 0; q < 4; q++) acc[i][j][q] = 0.0f;

    const int NK = K / KT;

#pragma unroll
    for (int s = 0; s < 2; s++) {
        uint32_t st = sb0 + s * STAGE_B;
        load_oper(st,          pA, K, s * KT, tid);
        load_oper(st + OPER_B, pB, K, s * KT, tid);
        asm volatile("cp.async.commit_group;" ::: "memory");
    }

    const int g8 = lane >> 3, lr = lane & 7;
    const int a_roff = ((g8 & 1) << 3) + lr, a_koff = g8 >> 1;
    const int b_roff = ((g8 >> 1) << 3) + lr, b_koff = g8 & 1;

    for (int ks = 0; ks < NK; ks++) {
        if (ks + 1 < NK) asm volatile("cp.async.wait_group 1;" ::: "memory");
        else             asm volatile("cp.async.wait_group 0;" ::: "memory");
        __syncthreads();

        if (ks + 2 < NK) {
            uint32_t st = sb0 + ((ks + 2) % NSTAGE) * STAGE_B;
            int ko = (ks + 2) * KT;
            load_oper(st,          pA, K, ko, tid);
            load_oper(st + OPER_B, pB, K, ko, tid);
            asm volatile("cp.async.commit_group;" ::: "memory");
        }

        const uint32_t st = sb0 + (ks % NSTAGE) * STAGE_B;
        const uint32_t sA_ = st, sB_ = st + OPER_B;

#pragma unroll
        for (int kk = 0; kk < 2; kk++) {
            uint32_t a[4][4], b[2][4];
#pragma unroll
            for (int mi = 0; mi < 4; mi++) {
                int row = warp_m * 64 + mi * 16 + a_roff;
                ldsm_x4(a[mi], sw_addr(sA_, row, kk * 2 + a_koff));
            }
#pragma unroll
            for (int np = 0; np < 2; np++) {
                int row = warp_n * 32 + np * 16 + b_roff;
                ldsm_x4(b[np], sw_addr(sB_, row, kk * 2 + b_koff));
            }
#pragma unroll
            for (int mi = 0; mi < 4; mi++)
#pragma unroll
                for (int nt = 0; nt < 4; nt++) {
                    const int np = nt >> 1, t = nt & 1;
                    mma_f16(acc[mi][nt], a[mi], b[np][2 * t], b[np][2 * t + 1]);
                }
        }
    }

    // ---------------- epilogue ----------------
#pragma unroll
    for (int mi = 0; mi < 4; mi++) {
#pragma unroll
        for (int h = 0; h < 2; h++) {
            const int grow = bm * 128 + warp_m * 64 + mi * 16 + h * 8 + (lane >> 2);
#pragma unroll
            for (int nt = 0; nt < 4; nt++) {
                const int col = bn * 128 + warp_n * 32 + (nt >> 1) * 16 + (nt & 1) * 8
                              + 2 * (lane & 3);
                float v0 = acc[mi][nt][2 * h];
                float v1 = acc[mi][nt][2 * h + 1];
                if constexpr (MODE == 0) {
                    v0 += g_bias[bz][col];
                    v1 += g_bias[bz][col + 1];
                    if (bz == 2) {
                        // Vt[batch][d=col][s]
                        const int batch = grow >> 11, s = grow & 2047;
                        const size_t idx = (size_t)batch * D_ * S_ + (size_t)col * S_ + s;
                        g_Vtf[idx]      = __float2half_rn(v0);
                        g_Vtf[idx + S_] = __float2half_rn(v1);
                    } else {
                        __half* dst = (bz == 0) ? g_Qf : g_Kf;
                        __half2 o = __floats2half2_rn(v0, v1);
                        *reinterpret_cast<__half2*>(dst + (size_t)grow * D_ + col) = o;
                    }
                } else {
                    const float scale = (MODE == 2) ? 0.03125f : 1.0f;
                    float2 o = make_float2(v0 * scale, v1 * scale);
                    *reinterpret_cast<float2*>(Cf + (size_t)bz * sC + (size_t)grow * ldc + col) = o;
                }
            }
        }
    }
}

// ---------------------------------------------------------------------------
// fp32 -> fp16 convert (elementwise, vectorized)
// ---------------------------------------------------------------------------
__global__ void __launch_bounds__(256) cvt_kernel(
    const float* __restrict__ src, __half* __restrict__ dst, int n)
{
    int i = (blockIdx.x * 256 + threadIdx.x) * 4;
    if (i >= n) return;
    float4 v = *reinterpret_cast<const float4*>(src + i);
    __half2 a = __floats2half2_rn(v.x, v.y);
    __half2 b = __floats2half2_rn(v.z, v.w);
    *reinterpret_cast<uint2*>(dst + i) =
        make_uint2(*reinterpret_cast<uint32_t*>(&a), *reinterpret_cast<uint32_t*>(&b));
}

// ---------------------------------------------------------------------------
// masked softmax over each score row; emits P as fp16
// ---------------------------------------------------------------------------
__global__ void __launch_bounds__(256) softmax_kernel(const int* __restrict__ mask)
{
    const int b = blockIdx.y, q = blockIdx.x, tid = threadIdx.x;
    const size_t rowoff = ((size_t)b * S_ + q) * S_;
    const float* row = g_S + rowoff;
    const int* m = mask + (size_t)b * S_;

    __shared__ float red[256];
    float v[8];
    float mx = -CUDART_INF_F;
#pragma unroll
    for (int i = 0; i < 8; i++) {
        int k = tid + i * 256;
        float s = row[k];
        v[i] = (m[k] != 0) ? s : -CUDART_INF_F;
        mx = fmaxf(mx, v[i]);
    }
    red[tid] = mx;
    __syncthreads();
    for (int s = 128; s > 0; s >>= 1) {
        if (tid < s) red[tid] = fmaxf(red[tid], red[tid + s]);
        __syncthreads();
    }
    mx = red[0];
    __syncthreads();

    float sum = 0.0f;
#pragma unroll
    for (int i = 0; i < 8; i++) {
        float e = __expf(v[i] - mx);
        v[i] = e;
        sum += e;
    }
    red[tid] = sum;
    __syncthreads();
    for (int s = 128; s > 0; s >>= 1) {
        if (tid < s) red[tid] += red[tid + s];
        __syncthreads();
    }
    const float inv = 1.0f / red[0];

#pragma unroll
    for (int i = 0; i < 8; i++) {
        int k = tid + i * 256;
        g_Pf[rowoff + k] = __float2half_rn(v[i] * inv);
    }
}

// ---------------------------------------------------------------------------
// Entry point (graph-capturable)
// ---------------------------------------------------------------------------
extern "C" void kernel_launch(void* const* d_in, const int* in_sizes, int n_in,
                              void* d_out, int out_size)
{
    const float* x    = (const float*)d_in[0];
    const int*   mask = (const int*)d_in[1];
    const float* Wq   = (const float*)d_in[2];
    const float* bq   = (const float*)d_in[3];
    const float* Wk   = (const float*)d_in[4];
    const float* bk   = (const float*)d_in[5];
    const float* Wv   = (const float*)d_in[6];
    const float* bv   = (const float*)d_in[7];
    float*       out  = (float*)d_out;

    cudaFuncSetAttribute(f16_gemm<0>, cudaFuncAttributeMaxDynamicSharedMemorySize, SMEM_GEMM);
    cudaFuncSetAttribute(f16_gemm<2>, cudaFuncAttributeMaxDynamicSharedMemorySize, SMEM_GEMM);
    cudaFuncSetAttribute(f16_gemm<3>, cudaFuncAttributeMaxDynamicSharedMemorySize, SMEM_GEMM);

    void *xf, *Wf, *Qf, *Kf, *Vtf, *Sp, *Pf, *bias;
    cudaGetSymbolAddress(&xf, g_xf);   cudaGetSymbolAddress(&Wf, g_Wf);
    cudaGetSymbolAddress(&Qf, g_Qf);   cudaGetSymbolAddress(&Kf, g_Kf);
    cudaGetSymbolAddress(&Vtf, g_Vtf); cudaGetSymbolAddress(&Sp, g_S);
    cudaGetSymbolAddress(&Pf, g_Pf);   cudaGetSymbolAddress(&bias, g_bias);

    __half *pxf = (__half*)xf, *pWf = (__half*)Wf;
    __half *pQf = (__half*)Qf, *pKf = (__half*)Kf, *pVtf = (__half*)Vtf, *pPf = (__half*)Pf;
    float* pS = (float*)Sp;
    float* pBias = (float*)bias;

    const int nx = MTOT * D_;   // 8,388,608
    const int nw = D_ * D_;     // 1,048,576

    cudaMemcpyAsync(pBias,          bq, D_ * sizeof(float), cudaMemcpyDeviceToDevice);
    cudaMemcpyAsync(pBias + D_,     bk, D_ * sizeof(float), cudaMemcpyDeviceToDevice);
    cudaMemcpyAsync(pBias + 2 * D_, bv, D_ * sizeof(float), cudaMemcpyDeviceToDevice);

    cvt_kernel<<<nx / 1024, 256>>>(x,  pxf,          nx);
    cvt_kernel<<<nw / 1024, 256>>>(Wq, pWf,          nw);
    cvt_kernel<<<nw / 1024, 256>>>(Wk, pWf + nw,     nw);
    cvt_kernel<<<nw / 1024, 256>>>(Wv, pWf + 2 * nw, nw);

    // fused QKV projections (fp16 single-pass): z selects weight/bias/output
    f16_gemm<0><<<dim3(8, 64, 3), 256, SMEM_GEMM>>>(
        pxf, pWf, nullptr, D_, D_, 0, (long long)nw, 0);
    // scores = Q @ K^T / 32 (fp32 out)
    f16_gemm<2><<<dim3(16, 16, B_), 256, SMEM_GEMM>>>(
        pQf, pKf, pS, D_, S_,
        (long long)S_ * D_, (long long)S_ * D_, (long long)S_ * S_);
    // masked softmax -> P fp16
    softmax_kernel<<<dim3(S_, B_), 256>>>(mask);
    // out = P @ Vt^T (fp32 direct to d_out)
    f16_gemm<3><<<dim3(8, 16, B_), 256, SMEM_GEMM>>>(
        pPf, pVtf, out, S_, D_,
        (long long)S_ * S_, (long long)D_ * S_, (long long)S_ * D_);
}

// round 8
// speedup vs baseline: 9.5805x; 1.2080x over previous
#include <cuda_runtime.h>
#include <cuda_fp16.h>
#include <math_constants.h>
#include <cstdint>

// Problem shape: B=4, S=2048, D=1024
#define B_ 4
#define S_ 2048
#define D_ 1024
#define MTOT (B_ * S_)   // 8192

// Tiling: CTA 128x128, Kt=32 fp16 per stage, 3 stages, 2 operands
#define KT 32
#define OPER_B 8192                        // 128 rows * 64B
#define NSTAGE 3
#define STAGE_B (2 * OPER_B)
#define SMEM_GEMM (NSTAGE * STAGE_B)       // 49152

// ---------------------------------------------------------------------------
// Scratch (device globals — allocation-free; zero-initialized at module load)
// ---------------------------------------------------------------------------
__device__ __half g_xf[MTOT * D_];                    // fp16 x
__device__ __half g_Wf[3][D_ * D_];                   // fp16 Wq/Wk/Wv
__device__ float  g_bias[3][D_];
__device__ __half g_Qf[MTOT * D_];                    // fp16 Q (full)
__device__ __half g_Kc[MTOT * D_];                    // fp16 K, COMPACTED rows [b][j][d]
__device__ __half g_Vtc[(size_t)B_ * D_ * S_];        // fp16 V^T, COMPACTED cols [b][d][j]
__device__ float  g_S[(size_t)B_ * S_ * S_];          // fp32 scores (cols < np used)
__device__ __half g_Pf[(size_t)B_ * S_ * S_];         // fp16 probs (cols < np used)
__device__ int    g_pos[MTOT];                        // compact position or -1
__device__ int    g_nv[B_];                           // valid key count per batch
__device__ int    g_np[B_];                           // nv padded to 128

// ---------------------------------------------------------------------------
// helpers
// ---------------------------------------------------------------------------
__device__ __forceinline__ uint32_t smem_u32(const void* p) {
    uint32_t a;
    asm("{ .reg .u64 t; cvta.to.shared.u64 t, %1; cvt.u32.u64 %0, t; }" : "=r"(a) : "l"(p));
    return a;
}
__device__ __forceinline__ uint32_t sw_addr(uint32_t base, int row, int kc) {
    int off = row * 64 + kc * 16;
    return base + (uint32_t)(off ^ ((off >> 3) & 0x30));
}
__device__ __forceinline__ void ldsm_x4(uint32_t* r, uint32_t addr) {
    asm volatile("ldmatrix.sync.aligned.m8n8.x4.shared.b16 {%0,%1,%2,%3}, [%4];"
                 : "=r"(r[0]), "=r"(r[1]), "=r"(r[2]), "=r"(r[3]) : "r"(addr));
}
__device__ __forceinline__ void mma_f16(float* c, const uint32_t* a, uint32_t b0, uint32_t b1) {
    asm volatile(
        "mma.sync.aligned.m16n8k16.row.col.f32.f16.f16.f32 "
        "{%0,%1,%2,%3}, {%4,%5,%6,%7}, {%8,%9}, {%0,%1,%2,%3};"
        : "+f"(c[0]), "+f"(c[1]), "+f"(c[2]), "+f"(c[3])
        : "r"(a[0]), "r"(a[1]), "r"(a[2]), "r"(a[3]), "r"(b0), "r"(b1));
}
__device__ __forceinline__ void load_oper(uint32_t sbase, const __half* __restrict__ g,
                                          int ld, int ko, int tid) {
#pragma unroll
    for (int j = 0; j < 2; j++) {
        int idx = tid + j * 256;
        int r = idx >> 2, c = idx & 3;
        uint32_t so = sw_addr(sbase, r, c);
        size_t ga = __cvta_generic_to_global(g + (size_t)r * ld + ko + c * 8);
        asm volatile("cp.async.cg.shared.global [%0], [%1], 16;" :: "r"(so), "l"(ga) : "memory");
    }
}

// ---------------------------------------------------------------------------
// compact: per-batch prefix scan of mask -> pos / nv / np
// ---------------------------------------------------------------------------
__global__ void __launch_bounds__(256) compact_kernel(const int* __restrict__ mask)
{
    const int b = blockIdx.x, tid = threadIdx.x;
    const int* m = mask + (size_t)b * S_;
    int flags[8], c = 0;
#pragma unroll
    for (int i = 0; i < 8; i++) {
        flags[i] = (m[tid * 8 + i] != 0);
        c += flags[i];
    }
    __shared__ int sc[256];
    sc[tid] = c;
    __syncthreads();
    for (int off = 1; off < 256; off <<= 1) {
        int v = (tid >= off) ? sc[tid - off] : 0;
        __syncthreads();
        sc[tid] += v;
        __syncthreads();
    }
    int p = sc[tid] - c;            // exclusive prefix
    const int total = sc[255];
#pragma unroll
    for (int i = 0; i < 8; i++) {
        g_pos[b * S_ + tid * 8 + i] = flags[i] ? p : -1;
        p += flags[i];
    }
    if (tid == 0) {
        g_nv[b] = total;
        g_np[b] = (total + 127) & ~127;
    }
}

// ---------------------------------------------------------------------------
// Single-pass fp16 NT GEMM: C[M,N] = A[M,K] * B[N,K]^T
// MODE 0: QKV projection (grid.z: 0=Q full, 1=K compacted, 2=V -> Vt compacted)
// MODE 2: scores = *1/32 -> fp32; N limited to np[bz] (block early-exit)
// MODE 3: PV -> fp32 out; K-dim = np[bz] (runtime loop bound)
// ---------------------------------------------------------------------------
template<int MODE>
__global__ void __launch_bounds__(256) f16_gemm(
    const __half* __restrict__ A, const __half* __restrict__ B,
    float* __restrict__ Cf,
    int K, int ldc, long long sA, long long sB, long long sC)
{
    const int bn = blockIdx.x, bm = blockIdx.y, bz = blockIdx.z;
    if constexpr (MODE == 2) {
        if (bn * 128 >= g_np[bz]) return;   // masked-away key tiles
    }

    extern __shared__ char smem[];
    const uint32_t sb0 = smem_u32(smem);
    const int tid = threadIdx.x;
    const int lane = tid & 31, wid = tid >> 5;
    const int warp_m = wid >> 2, warp_n = wid & 3;

    const __half* pA = A + (size_t)bz * sA + (size_t)bm * 128 * K;
    const __half* pB = B + (size_t)bz * sB + (size_t)bn * 128 * K;

    float acc[4][4][4];
#pragma unroll
    for (int i = 0; i < 4; i++)
#pragma unroll
        for (int j = 0; j < 4; j++)
#pragma unroll
            for (int q = 0; q < 4; q++) acc[i][j][q] = 0.0f;

    int Kloop = K;
    if constexpr (MODE == 3) Kloop = g_np[bz];
    const int NK = Kloop / KT;

#pragma unroll
    for (int s = 0; s < 2; s++) {
        uint32_t st = sb0 + s * STAGE_B;
        load_oper(st,          pA, K, s * KT, tid);
        load_oper(st + OPER_B, pB, K, s * KT, tid);
        asm volatile("cp.async.commit_group;" ::: "memory");
    }

    const int g8 = lane >> 3, lr = lane & 7;
    const int a_roff = ((g8 & 1) << 3) + lr, a_koff = g8 >> 1;
    const int b_roff = ((g8 >> 1) << 3) + lr, b_koff = g8 & 1;

    for (int ks = 0; ks < NK; ks++) {
        if (ks + 1 < NK) asm volatile("cp.async.wait_group 1;" ::: "memory");
        else             asm volatile("cp.async.wait_group 0;" ::: "memory");
        __syncthreads();

        if (ks + 2 < NK) {
            uint32_t st = sb0 + ((ks + 2) % NSTAGE) * STAGE_B;
            int ko = (ks + 2) * KT;
            load_oper(st,          pA, K, ko, tid);
            load_oper(st + OPER_B, pB, K, ko, tid);
            asm volatile("cp.async.commit_group;" ::: "memory");
        }

        const uint32_t st = sb0 + (ks % NSTAGE) * STAGE_B;
        const uint32_t sA_ = st, sB_ = st + OPER_B;

#pragma unroll
        for (int kk = 0; kk < 2; kk++) {
            uint32_t a[4][4], b[2][4];
#pragma unroll
            for (int mi = 0; mi < 4; mi++) {
                int row = warp_m * 64 + mi * 16 + a_roff;
                ldsm_x4(a[mi], sw_addr(sA_, row, kk * 2 + a_koff));
            }
#pragma unroll
            for (int np = 0; np < 2; np++) {
                int row = warp_n * 32 + np * 16 + b_roff;
                ldsm_x4(b[np], sw_addr(sB_, row, kk * 2 + b_koff));
            }
#pragma unroll
            for (int mi = 0; mi < 4; mi++)
#pragma unroll
                for (int nt = 0; nt < 4; nt++) {
                    const int np = nt >> 1, t = nt & 1;
                    mma_f16(acc[mi][nt], a[mi], b[np][2 * t], b[np][2 * t + 1]);
                }
        }
    }

    // ---------------- epilogue ----------------
#pragma unroll
    for (int mi = 0; mi < 4; mi++) {
#pragma unroll
        for (int h = 0; h < 2; h++) {
            const int grow = bm * 128 + warp_m * 64 + mi * 16 + h * 8 + (lane >> 2);
#pragma unroll
            for (int nt = 0; nt < 4; nt++) {
                const int col = bn * 128 + warp_n * 32 + (nt >> 1) * 16 + (nt & 1) * 8
                              + 2 * (lane & 3);
                float v0 = acc[mi][nt][2 * h];
                float v1 = acc[mi][nt][2 * h + 1];
                if constexpr (MODE == 0) {
                    v0 += g_bias[bz][col];
                    v1 += g_bias[bz][col + 1];
                    const int batch = grow >> 11;
                    if (bz == 0) {
                        __half2 o = __floats2half2_rn(v0, v1);
                        *reinterpret_cast<__half2*>(g_Qf + (size_t)grow * D_ + col) = o;
                    } else {
                        const int p = g_pos[grow];   // compact position of key s
                        if (p >= 0) {
                            if (bz == 1) {
                                __half2 o = __floats2half2_rn(v0, v1);
                                *reinterpret_cast<__half2*>(
                                    g_Kc + ((size_t)batch * S_ + p) * D_ + col) = o;
                            } else {
                                // Vtc[batch][d=col][j=p]
                                const size_t idx =
                                    (size_t)batch * D_ * S_ + (size_t)col * S_ + p;
                                g_Vtc[idx]      = __float2half_rn(v0);
                                g_Vtc[idx + S_] = __float2half_rn(v1);
                            }
                        }
                    }
                } else {
                    const float scale = (MODE == 2) ? 0.03125f : 1.0f;
                    float2 o = make_float2(v0 * scale, v1 * scale);
                    *reinterpret_cast<float2*>(Cf + (size_t)bz * sC + (size_t)grow * ldc + col) = o;
                }
            }
        }
    }
}

// ---------------------------------------------------------------------------
// fp32 -> fp16 convert (elementwise, vectorized)
// ---------------------------------------------------------------------------
__global__ void __launch_bounds__(256) cvt_kernel(
    const float* __restrict__ src, __half* __restrict__ dst, int n)
{
    int i = (blockIdx.x * 256 + threadIdx.x) * 4;
    if (i >= n) return;
    float4 v = *reinterpret_cast<const float4*>(src + i);
    __half2 a = __floats2half2_rn(v.x, v.y);
    __half2 b = __floats2half2_rn(v.z, v.w);
    *reinterpret_cast<uint2*>(dst + i) =
        make_uint2(*reinterpret_cast<uint32_t*>(&a), *reinterpret_cast<uint32_t*>(&b));
}

// ---------------------------------------------------------------------------
// softmax over compacted scores: k < nv valid, P=0 on [nv, np)
// ---------------------------------------------------------------------------
__global__ void __launch_bounds__(256) softmax_kernel()
{
    const int b = blockIdx.y, q = blockIdx.x, tid = threadIdx.x;
    const size_t rowoff = ((size_t)b * S_ + q) * S_;
    const float* row = g_S + rowoff;
    const int nv = g_nv[b], np = g_np[b];

    __shared__ float red[256];
    float v[8];
    float mx = -CUDART_INF_F;
#pragma unroll
    for (int i = 0; i < 8; i++) {
        int k = tid + i * 256;
        v[i] = (k < nv) ? row[k] : -CUDART_INF_F;
        mx = fmaxf(mx, v[i]);
    }
    red[tid] = mx;
    __syncthreads();
    for (int s = 128; s > 0; s >>= 1) {
        if (tid < s) red[tid] = fmaxf(red[tid], red[tid + s]);
        __syncthreads();
    }
    mx = red[0];
    __syncthreads();

    float sum = 0.0f;
#pragma unroll
    for (int i = 0; i < 8; i++) {
        float e = __expf(v[i] - mx);
        v[i] = e;
        sum += e;
    }
    red[tid] = sum;
    __syncthreads();
    for (int s = 128; s > 0; s >>= 1) {
        if (tid < s) red[tid] += red[tid + s];
        __syncthreads();
    }
    const float inv = 1.0f / red[0];

#pragma unroll
    for (int i = 0; i < 8; i++) {
        int k = tid + i * 256;
        if (k < np)
            g_Pf[rowoff + k] = __float2half_rn((k < nv) ? v[i] * inv : 0.0f);
    }
}

// ---------------------------------------------------------------------------
// Entry point (graph-capturable)
// ---------------------------------------------------------------------------
extern "C" void kernel_launch(void* const* d_in, const int* in_sizes, int n_in,
                              void* d_out, int out_size)
{
    const float* x    = (const float*)d_in[0];
    const int*   mask = (const int*)d_in[1];
    const float* Wq   = (const float*)d_in[2];
    const float* bq   = (const float*)d_in[3];
    const float* Wk   = (const float*)d_in[4];
    const float* bk   = (const float*)d_in[5];
    const float* Wv   = (const float*)d_in[6];
    const float* bv   = (const float*)d_in[7];
    float*       out  = (float*)d_out;

    cudaFuncSetAttribute(f16_gemm<0>, cudaFuncAttributeMaxDynamicSharedMemorySize, SMEM_GEMM);
    cudaFuncSetAttribute(f16_gemm<2>, cudaFuncAttributeMaxDynamicSharedMemorySize, SMEM_GEMM);
    cudaFuncSetAttribute(f16_gemm<3>, cudaFuncAttributeMaxDynamicSharedMemorySize, SMEM_GEMM);

    void *xf, *Wf, *Qf, *Kc, *Vtc, *Sp, *Pf, *bias;
    cudaGetSymbolAddress(&xf, g_xf);   cudaGetSymbolAddress(&Wf, g_Wf);
    cudaGetSymbolAddress(&Qf, g_Qf);   cudaGetSymbolAddress(&Kc, g_Kc);
    cudaGetSymbolAddress(&Vtc, g_Vtc); cudaGetSymbolAddress(&Sp, g_S);
    cudaGetSymbolAddress(&Pf, g_Pf);   cudaGetSymbolAddress(&bias, g_bias);

    __half *pxf = (__half*)xf, *pWf = (__half*)Wf;
    __half *pQf = (__half*)Qf, *pKc = (__half*)Kc, *pVtc = (__half*)Vtc, *pPf = (__half*)Pf;
    float* pS = (float*)Sp;
    float* pBias = (float*)bias;

    const int nx = MTOT * D_;
    const int nw = D_ * D_;

    cudaMemcpyAsync(pBias,          bq, D_ * sizeof(float), cudaMemcpyDeviceToDevice);
    cudaMemcpyAsync(pBias + D_,     bk, D_ * sizeof(float), cudaMemcpyDeviceToDevice);
    cudaMemcpyAsync(pBias + 2 * D_, bv, D_ * sizeof(float), cudaMemcpyDeviceToDevice);

    compact_kernel<<<B_, 256>>>(mask);

    cvt_kernel<<<nx / 1024, 256>>>(x,  pxf,          nx);
    cvt_kernel<<<nw / 1024, 256>>>(Wq, pWf,          nw);
    cvt_kernel<<<nw / 1024, 256>>>(Wk, pWf + nw,     nw);
    cvt_kernel<<<nw / 1024, 256>>>(Wv, pWf + 2 * nw, nw);

    // fused QKV projections; K/V epilogues write compacted layouts
    f16_gemm<0><<<dim3(8, 64, 3), 256, SMEM_GEMM>>>(
        pxf, pWf, nullptr, D_, D_, 0, (long long)nw, 0);
    // scores[b][q][j<np] = Q @ Kc^T / 32
    f16_gemm<2><<<dim3(16, 16, B_), 256, SMEM_GEMM>>>(
        pQf, pKc, pS, D_, S_,
        (long long)S_ * D_, (long long)S_ * D_, (long long)S_ * S_);
    // softmax over valid keys
    softmax_kernel<<<dim3(S_, B_), 256>>>();
    // out = P @ Vtc^T with K-dim = np[b]
    f16_gemm<3><<<dim3(8, 16, B_), 256, SMEM_GEMM>>>(
        pPf, pVtc, out, S_, D_,
        (long long)S_ * S_, (long long)D_ * S_, (long long)S_ * D_);
}

// round 9
// speedup vs baseline: 11.5903x; 1.2098x over previous
#include <cuda_runtime.h>
#include <cuda_fp16.h>
#include <math_constants.h>
#include <cstdint>

// Problem shape: B=4, S=2048, D=1024
#define B_ 4
#define S_ 2048
#define D_ 1024
#define MTOT (B_ * S_)   // 8192

// Tiling: CTA 128x128, Kt=32 fp16 per stage, 3 stages, 2 operands
#define KT 32
#define OPER_B 8192                        // 128 rows * 64B
#define NSTAGE 3
#define STAGE_B (2 * OPER_B)
#define SMEM_GEMM (NSTAGE * STAGE_B)       // 49152

// ---------------------------------------------------------------------------
// Scratch (device globals — allocation-free; zero-initialized at module load)
// ---------------------------------------------------------------------------
__device__ __half g_xf[MTOT * D_];                    // fp16 x (full rows)
__device__ __half g_xc[MTOT * D_];                    // fp16 x, compacted rows [b][j][d]
__device__ __half g_Wf[3][D_ * D_];                   // fp16 Wq/Wk/Wv
__device__ float  g_bias[3][D_];
__device__ __half g_Qf[MTOT * D_];                    // fp16 Q (full)
__device__ __half g_Kc[MTOT * D_];                    // fp16 K, compacted rows [b][j][d]
__device__ __half g_Vtc[(size_t)B_ * D_ * S_];        // fp16 V^T, compacted cols [b][d][j]
__device__ float  g_S[(size_t)B_ * S_ * S_];          // fp32 scores (cols < np used)
__device__ __half g_Pf[(size_t)B_ * S_ * S_];         // fp16 probs (cols < np used)
__device__ int    g_pos[MTOT];                        // compact position or -1
__device__ int    g_nv[B_];                           // valid key count per batch
__device__ int    g_np[B_];                           // nv padded to 128

// ---------------------------------------------------------------------------
// helpers
// ---------------------------------------------------------------------------
__device__ __forceinline__ uint32_t smem_u32(const void* p) {
    uint32_t a;
    asm("{ .reg .u64 t; cvta.to.shared.u64 t, %1; cvt.u32.u64 %0, t; }" : "=r"(a) : "l"(p));
    return a;
}
__device__ __forceinline__ uint32_t sw_addr(uint32_t base, int row, int kc) {
    int off = row * 64 + kc * 16;
    return base + (uint32_t)(off ^ ((off >> 3) & 0x30));
}
__device__ __forceinline__ void ldsm_x4(uint32_t* r, uint32_t addr) {
    asm volatile("ldmatrix.sync.aligned.m8n8.x4.shared.b16 {%0,%1,%2,%3}, [%4];"
                 : "=r"(r[0]), "=r"(r[1]), "=r"(r[2]), "=r"(r[3]) : "r"(addr));
}
__device__ __forceinline__ void mma_f16(float* c, const uint32_t* a, uint32_t b0, uint32_t b1) {
    asm volatile(
        "mma.sync.aligned.m16n8k16.row.col.f32.f16.f16.f32 "
        "{%0,%1,%2,%3}, {%4,%5,%6,%7}, {%8,%9}, {%0,%1,%2,%3};"
        : "+f"(c[0]), "+f"(c[1]), "+f"(c[2]), "+f"(c[3])
        : "r"(a[0]), "r"(a[1]), "r"(a[2]), "r"(a[3]), "r"(b0), "r"(b1));
}
__device__ __forceinline__ void load_oper(uint32_t sbase, const __half* __restrict__ g,
                                          int ld, int ko, int tid) {
#pragma unroll
    for (int j = 0; j < 2; j++) {
        int idx = tid + j * 256;
        int r = idx >> 2, c = idx & 3;
        uint32_t so = sw_addr(sbase, r, c);
        size_t ga = __cvta_generic_to_global(g + (size_t)r * ld + ko + c * 8);
        asm volatile("cp.async.cg.shared.global [%0], [%1], 16;" :: "r"(so), "l"(ga) : "memory");
    }
}

// ---------------------------------------------------------------------------
// compact: per-batch prefix scan of mask -> pos / nv / np
// ---------------------------------------------------------------------------
__global__ void __launch_bounds__(256) compact_kernel(const int* __restrict__ mask)
{
    const int b = blockIdx.x, tid = threadIdx.x;
    const int* m = mask + (size_t)b * S_;
    int flags[8], c = 0;
#pragma unroll
    for (int i = 0; i < 8; i++) {
        flags[i] = (m[tid * 8 + i] != 0);
        c += flags[i];
    }
    __shared__ int sc[256];
    sc[tid] = c;
    __syncthreads();
    for (int off = 1; off < 256; off <<= 1) {
        int v = (tid >= off) ? sc[tid - off] : 0;
        __syncthreads();
        sc[tid] += v;
        __syncthreads();
    }
    int p = sc[tid] - c;            // exclusive prefix
    const int total = sc[255];
#pragma unroll
    for (int i = 0; i < 8; i++) {
        g_pos[b * S_ + tid * 8 + i] = flags[i] ? p : -1;
        p += flags[i];
    }
    if (tid == 0) {
        g_nv[b] = total;
        g_np[b] = (total + 127) & ~127;
    }
}

// ---------------------------------------------------------------------------
// prep: fused fp32->fp16 conversion of x (+ compacted gather), W, and bias copy
// blocks [0,8192): x ; [8192,11264): W ; [11264,11267): bias
// ---------------------------------------------------------------------------
__global__ void __launch_bounds__(256) prep_kernel(
    const float* __restrict__ x,
    const float* __restrict__ Wq, const float* __restrict__ Wk, const float* __restrict__ Wv,
    const float* __restrict__ bq, const float* __restrict__ bk, const float* __restrict__ bv)
{
    const int blk = blockIdx.x, tid = threadIdx.x;
    if (blk < 8192) {
        const int i = blk * 1024 + tid * 4;
        float4 v = *reinterpret_cast<const float4*>(x + i);
        __half2 a = __floats2half2_rn(v.x, v.y);
        __half2 b = __floats2half2_rn(v.z, v.w);
        uint2 pk = make_uint2(*reinterpret_cast<uint32_t*>(&a),
                              *reinterpret_cast<uint32_t*>(&b));
        *reinterpret_cast<uint2*>(g_xf + i) = pk;
        const int row = i >> 10;
        const int p = g_pos[row];
        if (p >= 0) {
            const int batch = row >> 11;
            const int col = i & 1023;
            *reinterpret_cast<uint2*>(
                g_xc + (((size_t)(batch * S_ + p)) << 10) + col) = pk;
        }
    } else if (blk < 8192 + 3072) {
        const int wi = blk - 8192;
        const int w = wi >> 10;
        const int i = (wi & 1023) * 1024 + tid * 4;
        const float* src = (w == 0) ? Wq : (w == 1) ? Wk : Wv;
        float4 v = *reinterpret_cast<const float4*>(src + i);
        __half2 a = __floats2half2_rn(v.x, v.y);
        __half2 b = __floats2half2_rn(v.z, v.w);
        *reinterpret_cast<uint2*>(&g_Wf[w][i]) =
            make_uint2(*reinterpret_cast<uint32_t*>(&a), *reinterpret_cast<uint32_t*>(&b));
    } else {
        const int w = blk - 8192 - 3072;
        const float* src = (w == 0) ? bq : (w == 1) ? bk : bv;
        for (int j = tid; j < D_; j += 256) g_bias[w][j] = src[j];
    }
}

// ---------------------------------------------------------------------------
// Single-pass fp16 NT GEMM: C[M,N] = A[M,K] * B[N,K]^T
// MODE 0: Q projection (full 8192 rows) -> Qf fp16
// MODE 1: K/V projection over COMPACTED x. z = b*2 + kv. M limited to np[b].
//         kv=0 -> Kc rows; kv=1 -> Vtc transposed cols.
// MODE 2: scores = *1/32 -> fp32; N limited to np[bz]
// MODE 3: PV -> fp32 out; K-dim = np[bz]
// ---------------------------------------------------------------------------
template<int MODE>
__global__ void __launch_bounds__(256) f16_gemm(
    const __half* __restrict__ A, const __half* __restrict__ B,
    float* __restrict__ Cf,
    int K, int ldc, long long sA, long long sB, long long sC)
{
    const int bn = blockIdx.x, bm = blockIdx.y, bz = blockIdx.z;
    int batch = bz, kv = 0;
    if constexpr (MODE == 1) {
        batch = bz >> 1; kv = bz & 1;
        if (bm * 128 >= g_np[batch]) return;   // beyond valid-key rows
    }
    if constexpr (MODE == 2) {
        if (bn * 128 >= g_np[bz]) return;      // masked-away key tiles
    }

    extern __shared__ char smem[];
    const uint32_t sb0 = smem_u32(smem);
    const int tid = threadIdx.x;
    const int lane = tid & 31, wid = tid >> 5;
    const int warp_m = wid >> 2, warp_n = wid & 3;

    const __half* pA;
    const __half* pB;
    if constexpr (MODE == 1) {
        pA = A + (size_t)batch * (S_ * D_) + (size_t)bm * 128 * K;
        pB = B + (size_t)kv * (D_ * D_) + (size_t)bn * 128 * K;
    } else {
        pA = A + (size_t)bz * sA + (size_t)bm * 128 * K;
        pB = B + (size_t)bz * sB + (size_t)bn * 128 * K;
    }

    float acc[4][4][4];
#pragma unroll
    for (int i = 0; i < 4; i++)
#pragma unroll
        for (int j = 0; j < 4; j++)
#pragma unroll
            for (int q = 0; q < 4; q++) acc[i][j][q] = 0.0f;

    int Kloop = K;
    if constexpr (MODE == 3) Kloop = g_np[bz];
    const int NK = Kloop / KT;

#pragma unroll
    for (int s = 0; s < 2; s++) {
        uint32_t st = sb0 + s * STAGE_B;
        load_oper(st,          pA, K, s * KT, tid);
        load_oper(st + OPER_B, pB, K, s * KT, tid);
        asm volatile("cp.async.commit_group;" ::: "memory");
    }

    const int g8 = lane >> 3, lr = lane & 7;
    const int a_roff = ((g8 & 1) << 3) + lr, a_koff = g8 >> 1;
    const int b_roff = ((g8 >> 1) << 3) + lr, b_koff = g8 & 1;

    for (int ks = 0; ks < NK; ks++) {
        if (ks + 1 < NK) asm volatile("cp.async.wait_group 1;" ::: "memory");
        else             asm volatile("cp.async.wait_group 0;" ::: "memory");
        __syncthreads();

        if (ks + 2 < NK) {
            uint32_t st = sb0 + ((ks + 2) % NSTAGE) * STAGE_B;
            int ko = (ks + 2) * KT;
            load_oper(st,          pA, K, ko, tid);
            load_oper(st + OPER_B, pB, K, ko, tid);
            asm volatile("cp.async.commit_group;" ::: "memory");
        }

        const uint32_t st = sb0 + (ks % NSTAGE) * STAGE_B;
        const uint32_t sA_ = st, sB_ = st + OPER_B;

#pragma unroll
        for (int kk = 0; kk < 2; kk++) {
            uint32_t a[4][4], b[2][4];
#pragma unroll
            for (int mi = 0; mi < 4; mi++) {
                int row = warp_m * 64 + mi * 16 + a_roff;
                ldsm_x4(a[mi], sw_addr(sA_, row, kk * 2 + a_koff));
            }
#pragma unroll
            for (int np = 0; np < 2; np++) {
                int row = warp_n * 32 + np * 16 + b_roff;
                ldsm_x4(b[np], sw_addr(sB_, row, kk * 2 + b_koff));
            }
#pragma unroll
            for (int mi = 0; mi < 4; mi++)
#pragma unroll
                for (int nt = 0; nt < 4; nt++) {
                    const int np = nt >> 1, t = nt & 1;
                    mma_f16(acc[mi][nt], a[mi], b[np][2 * t], b[np][2 * t + 1]);
                }
        }
    }

    // ---------------- epilogue ----------------
#pragma unroll
    for (int mi = 0; mi < 4; mi++) {
#pragma unroll
        for (int h = 0; h < 2; h++) {
            const int grow = bm * 128 + warp_m * 64 + mi * 16 + h * 8 + (lane >> 2);
#pragma unroll
            for (int nt = 0; nt < 4; nt++) {
                const int col = bn * 128 + warp_n * 32 + (nt >> 1) * 16 + (nt & 1) * 8
                              + 2 * (lane & 3);
                float v0 = acc[mi][nt][2 * h];
                float v1 = acc[mi][nt][2 * h + 1];
                if constexpr (MODE == 0) {
                    v0 += g_bias[0][col];
                    v1 += g_bias[0][col + 1];
                    __half2 o = __floats2half2_rn(v0, v1);
                    *reinterpret_cast<__half2*>(g_Qf + (size_t)grow * D_ + col) = o;
                } else if constexpr (MODE == 1) {
                    v0 += g_bias[1 + kv][col];
                    v1 += g_bias[1 + kv][col + 1];
                    if (kv == 0) {
                        __half2 o = __floats2half2_rn(v0, v1);
                        *reinterpret_cast<__half2*>(
                            g_Kc + ((size_t)batch * S_ + grow) * D_ + col) = o;
                    } else {
                        // Vtc[batch][d=col][j=grow]
                        const size_t idx = (size_t)batch * D_ * S_ + (size_t)col * S_ + grow;
                        g_Vtc[idx]      = __float2half_rn(v0);
                        g_Vtc[idx + S_] = __float2half_rn(v1);
                    }
                } else {
                    const float scale = (MODE == 2) ? 0.03125f : 1.0f;
                    float2 o = make_float2(v0 * scale, v1 * scale);
                    *reinterpret_cast<float2*>(Cf + (size_t)bz * sC + (size_t)grow * ldc + col) = o;
                }
            }
        }
    }
}

// ---------------------------------------------------------------------------
// softmax over compacted scores: k < nv valid, P=0 on [nv, np)
// ---------------------------------------------------------------------------
__global__ void __launch_bounds__(256) softmax_kernel()
{
    const int b = blockIdx.y, q = blockIdx.x, tid = threadIdx.x;
    const size_t rowoff = ((size_t)b * S_ + q) * S_;
    const float* row = g_S + rowoff;
    const int nv = g_nv[b], np = g_np[b];

    __shared__ float red[256];
    float v[8];
    float mx = -CUDART_INF_F;
#pragma unroll
    for (int i = 0; i < 8; i++) {
        int k = tid + i * 256;
        v[i] = (k < nv) ? row[k] : -CUDART_INF_F;
        mx = fmaxf(mx, v[i]);
    }
    red[tid] = mx;
    __syncthreads();
    for (int s = 128; s > 0; s >>= 1) {
        if (tid < s) red[tid] = fmaxf(red[tid], red[tid + s]);
        __syncthreads();
    }
    mx = red[0];
    __syncthreads();

    float sum = 0.0f;
#pragma unroll
    for (int i = 0; i < 8; i++) {
        float e = __expf(v[i] - mx);
        v[i] = e;
        sum += e;
    }
    red[tid] = sum;
    __syncthreads();
    for (int s = 128; s > 0; s >>= 1) {
        if (tid < s) red[tid] += red[tid + s];
        __syncthreads();
    }
    const float inv = 1.0f / red[0];

#pragma unroll
    for (int i = 0; i < 8; i++) {
        int k = tid + i * 256;
        if (k < np)
            g_Pf[rowoff + k] = __float2half_rn((k < nv) ? v[i] * inv : 0.0f);
    }
}

// ---------------------------------------------------------------------------
// Entry point (graph-capturable)
// ---------------------------------------------------------------------------
extern "C" void kernel_launch(void* const* d_in, const int* in_sizes, int n_in,
                              void* d_out, int out_size)
{
    const float* x    = (const float*)d_in[0];
    const int*   mask = (const int*)d_in[1];
    const float* Wq   = (const float*)d_in[2];
    const float* bq   = (const float*)d_in[3];
    const float* Wk   = (const float*)d_in[4];
    const float* bk   = (const float*)d_in[5];
    const float* Wv   = (const float*)d_in[6];
    const float* bv   = (const float*)d_in[7];
    float*       out  = (float*)d_out;

    cudaFuncSetAttribute(f16_gemm<0>, cudaFuncAttributeMaxDynamicSharedMemorySize, SMEM_GEMM);
    cudaFuncSetAttribute(f16_gemm<1>, cudaFuncAttributeMaxDynamicSharedMemorySize, SMEM_GEMM);
    cudaFuncSetAttribute(f16_gemm<2>, cudaFuncAttributeMaxDynamicSharedMemorySize, SMEM_GEMM);
    cudaFuncSetAttribute(f16_gemm<3>, cudaFuncAttributeMaxDynamicSharedMemorySize, SMEM_GEMM);

    void *xf, *xc, *Wf, *Qf, *Kc, *Vtc, *Sp, *Pf;
    cudaGetSymbolAddress(&xf, g_xf);   cudaGetSymbolAddress(&xc, g_xc);
    cudaGetSymbolAddress(&Wf, g_Wf);
    cudaGetSymbolAddress(&Qf, g_Qf);   cudaGetSymbolAddress(&Kc, g_Kc);
    cudaGetSymbolAddress(&Vtc, g_Vtc); cudaGetSymbolAddress(&Sp, g_S);
    cudaGetSymbolAddress(&Pf, g_Pf);

    __half *pxf = (__half*)xf, *pxc = (__half*)xc, *pWf = (__half*)Wf;
    __half *pQf = (__half*)Qf, *pKc = (__half*)Kc, *pVtc = (__half*)Vtc, *pPf = (__half*)Pf;
    float* pS = (float*)Sp;

    const int nw = D_ * D_;

    // mask scan, then fused convert/gather/bias staging
    compact_kernel<<<B_, 256>>>(mask);
    prep_kernel<<<8192 + 3072 + 3, 256>>>(x, Wq, Wk, Wv, bq, bk, bv);

    // Q projection (full rows)
    f16_gemm<0><<<dim3(8, 64, 1), 256, SMEM_GEMM>>>(
        pxf, pWf, nullptr, D_, D_, 0, 0, 0);
    // K/V projections over compacted x: z = b*2 + (0=K, 1=V)
    f16_gemm<1><<<dim3(8, 16, 2 * B_), 256, SMEM_GEMM>>>(
        pxc, pWf + nw, nullptr, D_, D_, 0, 0, 0);
    // scores[b][q][j<np] = Q @ Kc^T / 32
    f16_gemm<2><<<dim3(16, 16, B_), 256, SMEM_GEMM>>>(
        pQf, pKc, pS, D_, S_,
        (long long)S_ * D_, (long long)S_ * D_, (long long)S_ * S_);
    // softmax over valid keys
    softmax_kernel<<<dim3(S_, B_), 256>>>();
    // out = P @ Vtc^T with K-dim = np[b]
    f16_gemm<3><<<dim3(8, 16, B_), 256, SMEM_GEMM>>>(
        pPf, pVtc, out, S_, D_,
        (long long)S_ * S_, (long long)D_ * S_, (long long)S_ * D_);
}